// round 4
// baseline (speedup 1.0000x reference)
#include <cuda_runtime.h>
#include <cuda_bf16.h>
#include <cstdint>

typedef unsigned long long ull;

#define PAIRS 1024
#define DD 256
#define QL 16

// ---------------- persistent scratch / precomputed ----------------
__device__ unsigned g_Au[128 * 256];       // bf16x2( A[2*d2][e], A[2*d2+1][e] )
__device__ float    g_WvT[256 * 256];      // WvT[j][d] = vw_w[d][j]
__device__ float    g_u[256];
__device__ float    g_w[256];
__device__ float    g_c;
__device__ int      g_mask_mode;           // 0=u8 bool, 1=int32, 2=float32
__device__ float    g_tvec[PAIRS * 256];   // attn . v  per pair
__device__ float    g_sA[PAIRS];           // 1 if any unmasked else 0

__device__ __forceinline__ unsigned f2bf(float a, float b) {
    __nv_bfloat162 h = __floats2bfloat162_rn(a, b);
    return *reinterpret_cast<unsigned*>(&h);
}
__device__ __forceinline__ ull pack2(float a, float b) {
    ull r; asm("mov.b64 %0, {%1,%2};" : "=l"(r) : "f"(a), "f"(b)); return r;
}
__device__ __forceinline__ float2 unpack2(ull v) {
    float2 f; asm("mov.b64 {%0,%1}, %2;" : "=f"(f.x), "=f"(f.y) : "l"(v)); return f;
}
// bf16x2 (lo,hi) -> f32x2 (lo,hi)
__device__ __forceinline__ ull bf2w(unsigned u) {
    return pack2(__uint_as_float(u << 16), __uint_as_float(u & 0xFFFF0000u));
}
#define FFMA2(d, a, b) asm("fma.rn.f32x2 %0, %1, %2, %0;" : "+l"(d) : "l"(a), "l"(b))

// ---------------- setup kernel ----------------
__global__ void setup_kernel(const float* __restrict__ qw_w, const float* __restrict__ qw_b,
                             const float* __restrict__ kw_w, const float* __restrict__ kw_b,
                             const float* __restrict__ vw_w, const void* __restrict__ maskp)
{
    const int b = blockIdx.x;
    const int t = threadIdx.x;
    if (b < 64) {
        // A rows 4b..4b+3 (col e=t), plus u rows, plus (block 0) w and c
        const int j0 = b * 4;
        float a0 = 0.f, a1 = 0.f, a2 = 0.f, a3 = 0.f;
        float u0 = 0.f, u1 = 0.f, u2 = 0.f, u3 = 0.f, wacc = 0.f;
        #pragma unroll 4
        for (int dd = 0; dd < 256; dd++) {
            float kv = kw_w[dd * 256 + t];
            float4 qv = *(const float4*)&qw_w[dd * 256 + j0];
            float kbv = __ldg(&kw_b[dd]);
            float qbv = __ldg(&qw_b[dd]);
            a0 += qv.x * kv; a1 += qv.y * kv; a2 += qv.z * kv; a3 += qv.w * kv;
            u0 += qv.x * kbv; u1 += qv.y * kbv; u2 += qv.z * kbv; u3 += qv.w * kbv;
            wacc += kv * qbv;
        }
        g_Au[(2 * b) * 256 + t]     = f2bf(a0, a1);
        g_Au[(2 * b + 1) * 256 + t] = f2bf(a2, a3);
        if (b == 0) g_w[t] = wacc;
        if (t == 0) { g_u[j0] = u0; g_u[j0 + 1] = u1; g_u[j0 + 2] = u2; g_u[j0 + 3] = u3; }
        if (b == 0 && t == 1) {
            float cc = 0.f;
            for (int i = 0; i < 256; i++) cc += qw_b[i] * kw_b[i];
            g_c = cc;
        }
    } else if (b == 64) {
        // mask dtype detection
        __shared__ int nf[2];
        if (t < 2) nf[t] = 0;
        __syncthreads();
        const unsigned* mw = (const unsigned*)maskp;
        int bad0 = 0, bad1 = 0;
        for (int i = t; i < 16384; i += 256) {   // 64KB, safe in all interpretations
            unsigned w = mw[i];
            if (w > 1u) bad0 = 1;
            if (w != 0u && w != 0x3F800000u) bad1 = 1;
        }
        if (bad0) nf[0] = 1;
        if (bad1) nf[1] = 1;
        __syncthreads();
        if (t == 0) g_mask_mode = nf[0] ? (nf[1] ? 0 : 2) : 1;
    } else {
        // WvT transpose: 64 blocks of 32x32 tiles
        __shared__ float s[32][33];
        const int bb = b - 65;
        const int di = (bb >> 3) * 32, jj = (bb & 7) * 32;
        const int tx = t & 31, ty = t >> 5;
        #pragma unroll
        for (int u2 = 0; u2 < 4; u2++)
            s[ty + 8 * u2][tx] = vw_w[(di + ty + 8 * u2) * 256 + (jj + tx)];
        __syncthreads();
        #pragma unroll
        for (int u2 = 0; u2 < 4; u2++)
            g_WvT[(jj + ty + 8 * u2) * 256 + (di + tx)] = s[tx][ty + 8 * u2];
    }
}

// ---------------- fused per-pair kernel ----------------
// smem layout (bytes):
//   [0,      66560)  kbf  : 128 rows x 130 uints (bf16x2 k tile); idx(e2)=e2+(e2>>6)
//   [66560,  82944)  qT2  : float2 (q[i][2d2], q[i][2d2+1]) at f2-index d2*16+i
//   [82944, 101408)  Qt   : float2 (Qt[i][e0], Qt[i][e1])  at f2-index e2*18 + (e2>>6)*4 + i
//                           (rows disjoint; group-1 rows skewed +32B = 8 banks)
//   [101408,102464)  ws2  : 132 ull f32x2 (w[2e2], w[2e2+1]) at idx e2 + 2*(e2>>6)
//   [102464,102528)  a_s  : 16 floats
//   [102528,103552)  ta_s : 256 floats
//   [103552,103584)  red_s: 8 floats
#define SM_QT2 66560
#define SM_QTT 82944
#define SM_WS2 101408
#define SM_A   102464
#define SM_TA  102528
#define SM_RED 103552
#define SM_TOT 103584

__device__ __forceinline__ float bsum(float v, float* red, int t) {
    __syncthreads();
    #pragma unroll
    for (int o = 16; o > 0; o >>= 1) v += __shfl_xor_sync(0xffffffffu, v, o);
    if ((t & 31) == 0) red[t >> 5] = v;
    __syncthreads();
    float r = red[0];
    #pragma unroll
    for (int i = 1; i < 8; i++) r += red[i];
    return r;
}
__device__ __forceinline__ float bmax(float v, float* red, int t) {
    __syncthreads();
    #pragma unroll
    for (int o = 16; o > 0; o >>= 1) v = fmaxf(v, __shfl_xor_sync(0xffffffffu, v, o));
    if ((t & 31) == 0) red[t >> 5] = v;
    __syncthreads();
    float r = red[0];
    #pragma unroll
    for (int i = 1; i < 8; i++) r = fmaxf(r, red[i]);
    return r;
}

__global__ void __launch_bounds__(256, 2)
fused_kernel(const float* __restrict__ q, const float* __restrict__ k,
             const float* __restrict__ v, const void* __restrict__ maskp)
{
    extern __shared__ unsigned char sm[];
    unsigned* kbf   = (unsigned*)sm;
    float2*   qT2f  = (float2*)(sm + SM_QT2);
    float2*   Qtf   = (float2*)(sm + SM_QTT);
    ull*      ws2   = (ull*)(sm + SM_WS2);
    float*    a_s   = (float*)(sm + SM_A);
    float*    ta_s  = (float*)(sm + SM_TA);
    float*    red_s = (float*)(sm + SM_RED);

    const int pair = blockIdx.x;
    const int t = threadIdx.x;
    const float* qb = q + (size_t)pair * QL * DD;
    const float* kb = k + (size_t)pair * 256 * DD;
    const float* vb = v + (size_t)pair * 256 * DD;

    // ---- stage qT2 (d-pair f32x2, transposed) + ws2 ----
    {
        const float4* qs = (const float4*)qb;   // 1024 float4
        #pragma unroll
        for (int it = 0; it < 4; it++) {
            int idx = it * 256 + t;
            float4 f = qs[idx];
            int i = idx >> 6;
            int d0 = (idx & 63) * 4;
            qT2f[(d0 >> 1) * 16 + i]       = make_float2(f.x, f.y);
            qT2f[((d0 >> 1) + 1) * 16 + i] = make_float2(f.z, f.w);
        }
        if (t < 128) {
            float2 wv = *(const float2*)&g_w[2 * t];
            ws2[t + 2 * (t >> 6)] = pack2(wv.x, wv.y);
        }
    }
    __syncthreads();

    // ---- Phase 1: Qt[i][e] = sum_d q[i][d]*A[d][e], f32x2 over d-pairs ----
    {
        const int p = t & 127;        // e-pair index
        const int ihalf = t >> 7;     // 8 i's each
        ull acc0[8], acc1[8];
        #pragma unroll
        for (int i = 0; i < 8; i++) { acc0[i] = 0ull; acc1[i] = 0ull; }
        const uint2* A2 = (const uint2*)g_Au;   // index d2*128 + p
        #pragma unroll 2
        for (int d2 = 0; d2 < 128; d2++) {
            uint2 a = A2[d2 * 128 + p];
            ull Ae0 = bf2w(a.x);
            ull Ae1 = bf2w(a.y);
            const ulonglong2* qp = (const ulonglong2*)(qT2f + d2 * 16 + ihalf * 8);
            ulonglong2 qA = qp[0], qB = qp[1], qC = qp[2], qD = qp[3];
            FFMA2(acc0[0], qA.x, Ae0); FFMA2(acc1[0], qA.x, Ae1);
            FFMA2(acc0[1], qA.y, Ae0); FFMA2(acc1[1], qA.y, Ae1);
            FFMA2(acc0[2], qB.x, Ae0); FFMA2(acc1[2], qB.x, Ae1);
            FFMA2(acc0[3], qB.y, Ae0); FFMA2(acc1[3], qB.y, Ae1);
            FFMA2(acc0[4], qC.x, Ae0); FFMA2(acc1[4], qC.x, Ae1);
            FFMA2(acc0[5], qC.y, Ae0); FFMA2(acc1[5], qC.y, Ae1);
            FFMA2(acc0[6], qD.x, Ae0); FFMA2(acc1[6], qD.x, Ae1);
            FFMA2(acc0[7], qD.y, Ae0); FFMA2(acc1[7], qD.y, Ae1);
        }
        const int base = p * 18 + (p >> 6) * 4;   // float2 units; rows disjoint
        #pragma unroll
        for (int i = 0; i < 8; i++) {
            float2 e0f = unpack2(acc0[i]);
            float2 e1f = unpack2(acc1[i]);
            Qtf[base + 8 * ihalf + i] = make_float2(e0f.x + e0f.y, e1f.x + e1f.y);
        }
    }
    // ---- a_i = q_i . u + c  (warp 0) ----
    if (t < 32) {
        const float cc = g_c;
        for (int i = 0; i < QL; i++) {
            float p = 0.f;
            #pragma unroll
            for (int dd = t; dd < 256; dd += 32) {
                float2 qv = qT2f[(dd >> 1) * 16 + i];
                p += ((dd & 1) ? qv.y : qv.x) * g_u[dd];
            }
            #pragma unroll
            for (int o = 16; o > 0; o >>= 1) p += __shfl_xor_sync(0xffffffffu, p, o);
            if (t == 0) a_s[i] = p + cc;
        }
    }

    // ---- Phase 2: scores + row max -> ta, two 128-row tiles ----
    const int r = t >> 1;     // row within tile
    const int h = t & 1;      // e-half
    for (int tile = 0; tile < 2; tile++) {
        __syncthreads();
        {   // stage k tile as bf16
            const float4* ks = (const float4*)(kb + tile * 128 * 256);
            #pragma unroll 4
            for (int it = 0; it < 32; it++) {
                int idx = it * 256 + t;     // 8192 float4
                float4 f = ks[idx];
                int row = idx >> 6;
                int c4 = idx & 63;
                int e2a = 2 * c4;
                int off = row * 130 + e2a + (e2a >> 6);
                kbf[off]     = f2bf(f.x, f.y);
                kbf[off + 1] = f2bf(f.z, f.w);
            }
        }
        __syncthreads();
        const unsigned* krow = kbf + r * 130 + 65 * h;
        const ull* wrow = ws2 + 66 * h;
        const float2* Qbase = Qtf + 1156 * h;   // base(64h+j) = j*18 + h*(64*18+4)
        ull acc2[16];
        #pragma unroll
        for (int i = 0; i < 16; i++) acc2[i] = 0ull;
        ull wk2 = 0ull;
        #pragma unroll 2
        for (int j = 0; j < 64; j++) {
            ull k2 = bf2w(krow[j]);
            ull w2 = wrow[j];
            FFMA2(wk2, w2, k2);
            const ulonglong2* Qp = (const ulonglong2*)(Qbase + j * 18);
            #pragma unroll
            for (int w = 0; w < 8; w++) {
                ulonglong2 qq = Qp[w];
                FFMA2(acc2[2 * w],     qq.x, k2);
                FFMA2(acc2[2 * w + 1], qq.y, k2);
            }
        }
        float sc[16];
        #pragma unroll
        for (int i = 0; i < 16; i++) {
            float2 f = unpack2(acc2[i]);
            sc[i] = f.x + f.y;
        }
        float2 wf = unpack2(wk2);
        float wk = wf.x + wf.y;
        #pragma unroll
        for (int i = 0; i < 16; i++) sc[i] += __shfl_xor_sync(0xffffffffu, sc[i], 1);
        wk += __shfl_xor_sync(0xffffffffu, wk, 1);
        if (h == 0) {
            float mx = -1e30f;
            #pragma unroll
            for (int i = 0; i < 16; i++) mx = fmaxf(mx, sc[i] + a_s[i]);
            ta_s[tile * 128 + r] = wk + mx;
        }
    }

    // ---- Phase 3: normalize, mask, softmax ----
    float cnt;
    {
        __syncthreads();
        float tv = ta_s[t];
        float ss = bsum(tv * tv, red_s, t);
        float inv = rsqrtf(ss);
        const int mm = g_mask_mode;
        bool masked;
        size_t mi = (size_t)pair * 256 + t;
        if (mm == 0)      masked = ((const unsigned char*)maskp)[mi] != 0;
        else if (mm == 1) masked = ((const int*)maskp)[mi] != 0;
        else              masked = ((const float*)maskp)[mi] != 0.f;
        float x = masked ? -10.f : tv * inv;
        cnt = bsum(masked ? 0.f : 1.f, red_s, t);
        float mx = bmax(x, red_s, t);
        float ex = __expf(x - mx);
        float se = bsum(ex, red_s, t);
        float attn = (cnt == 0.f) ? 0.f : ex / se;
        ta_s[t] = attn;
        __syncthreads();
    }

    // ---- Phase 4: tvec[j=t] = sum_v attn[v] * v[v][t] ----
    {
        float acc = 0.f;
        #pragma unroll 8
        for (int vv = 0; vv < 256; vv++)
            acc += ta_s[vv] * vb[vv * 256 + t];
        g_tvec[pair * 256 + t] = acc;
        if (t == 0) g_sA[pair] = (cnt > 0.f) ? 1.f : 0.f;
    }
}

// ---------------- output projection: OUT = TVEC @ WvT + sA*vb ----------------
__global__ void out_kernel(const float* __restrict__ vw_b, float* __restrict__ out)
{
    __shared__ float tvT[256 * 20];
    __shared__ float sA_s[16];
    __shared__ float vb_s[256];
    const int t = threadIdx.x;
    const int p0 = blockIdx.x * 16;
    vb_s[t] = vw_b[t];
    if (t < 16) sA_s[t] = g_sA[p0 + t];
    #pragma unroll
    for (int it = 0; it < 16; it++) {
        int idx = it * 256 + t;
        int r = idx >> 8, j = idx & 255;
        tvT[j * 20 + r] = g_tvec[(p0 + r) * 256 + j];
    }
    __syncthreads();
    float acc[16];
    #pragma unroll
    for (int r = 0; r < 16; r++) acc[r] = 0.f;
    #pragma unroll 4
    for (int j = 0; j < 256; j++) {
        float wv = g_WvT[j * 256 + t];
        const float4* T = (const float4*)&tvT[j * 20];
        float4 t0 = T[0], t1 = T[1], t2 = T[2], t3 = T[3];
        acc[0]  += t0.x * wv;  acc[1]  += t0.y * wv;
        acc[2]  += t0.z * wv;  acc[3]  += t0.w * wv;
        acc[4]  += t1.x * wv;  acc[5]  += t1.y * wv;
        acc[6]  += t1.z * wv;  acc[7]  += t1.w * wv;
        acc[8]  += t2.x * wv;  acc[9]  += t2.y * wv;
        acc[10] += t2.z * wv;  acc[11] += t2.w * wv;
        acc[12] += t3.x * wv;  acc[13] += t3.y * wv;
        acc[14] += t3.z * wv;  acc[15] += t3.w * wv;
    }
    #pragma unroll
    for (int r = 0; r < 16; r++)
        out[(size_t)(p0 + r) * 256 + t] = acc[r] + sA_s[r] * vb_s[t];
}

extern "C" void kernel_launch(void* const* d_in, const int* in_sizes, int n_in,
                              void* d_out, int out_size)
{
    const float* q    = (const float*)d_in[0];
    const float* k    = (const float*)d_in[1];
    const float* v    = (const float*)d_in[2];
    const void*  m    = d_in[3];
    const float* qw_w = (const float*)d_in[4];
    const float* qw_b = (const float*)d_in[5];
    const float* kw_w = (const float*)d_in[6];
    const float* kw_b = (const float*)d_in[7];
    const float* vw_w = (const float*)d_in[8];
    const float* vw_b = (const float*)d_in[9];
    float* out = (float*)d_out;
    (void)in_sizes; (void)n_in; (void)out_size;

    cudaFuncSetAttribute(fused_kernel, cudaFuncAttributeMaxDynamicSharedMemorySize, SM_TOT);

    setup_kernel<<<129, 256>>>(qw_w, qw_b, kw_w, kw_b, vw_w, m);
    fused_kernel<<<PAIRS, 256, SM_TOT>>>(q, k, v, m);
    out_kernel<<<64, 256>>>(vw_b, out);
}

// round 5
// speedup vs baseline: 1.2925x; 1.2925x over previous
#include <cuda_runtime.h>
#include <cuda_bf16.h>
#include <cstdint>

typedef unsigned long long ull;

#define PAIRS 1024
#define DD 256
#define QL 16

// ---------------- persistent scratch / precomputed ----------------
__device__ unsigned g_Au[128 * 256];       // bf16x2( A[2*d2][e], A[2*d2+1][e] ) at [d2*256+e]
__device__ float    g_WvT[256 * 256];      // WvT[j][d] = vw_w[d][j]
__device__ float    g_u[256];
__device__ float    g_w[256];
__device__ float    g_c;
__device__ int      g_mask_mode;           // 0=u8 bool, 1=int32, 2=float32
__device__ float    g_tvec[PAIRS * 256];   // attn . v  per pair
__device__ float    g_sA[PAIRS];           // 1 if any unmasked else 0

__device__ __forceinline__ unsigned f2bf(float a, float b) {
    __nv_bfloat162 h = __floats2bfloat162_rn(a, b);
    return *reinterpret_cast<unsigned*>(&h);
}
__device__ __forceinline__ ull pack2(float a, float b) {
    ull r; asm("mov.b64 %0, {%1,%2};" : "=l"(r) : "f"(a), "f"(b)); return r;
}
__device__ __forceinline__ float2 unpack2(ull v) {
    float2 f; asm("mov.b64 {%0,%1}, %2;" : "=f"(f.x), "=f"(f.y) : "l"(v)); return f;
}
// bf16x2 (lo,hi) -> f32x2 (lo,hi)
__device__ __forceinline__ ull bf2w(unsigned u) {
    return pack2(__uint_as_float(u << 16), __uint_as_float(u & 0xFFFF0000u));
}
#define FFMA2(d, a, b) asm("fma.rn.f32x2 %0, %1, %2, %0;" : "+l"(d) : "l"(a), "l"(b))

// ---------------- setup kernel (parallelism-first rewrite) ----------------
__global__ void setup_kernel(const float* __restrict__ qw_w, const float* __restrict__ qw_b,
                             const float* __restrict__ kw_w, const float* __restrict__ kw_b,
                             const float* __restrict__ vw_w, const void* __restrict__ maskp)
{
    const int b = blockIdx.x;
    const int t = threadIdx.x;
    if (b < 128) {
        // A rows j0=2b, 2b+1 (col e=t), packed bf16x2; plus u[2b], u[2b+1]
        const int j0 = 2 * b;
        float a0 = 0.f, a1 = 0.f;
        #pragma unroll 8
        for (int dd = 0; dd < 256; dd++) {
            float kv = kw_w[dd * 256 + t];
            float2 qv = *(const float2*)&qw_w[dd * 256 + j0];
            a0 += qv.x * kv;
            a1 += qv.y * kv;
        }
        g_Au[b * 256 + t] = f2bf(a0, a1);
        if (t < 64) {
            const int jj = j0 + (t >> 5);
            const int l = t & 31;
            float up = 0.f;
            #pragma unroll
            for (int m = 0; m < 8; m++)
                up += qw_w[(l + 32 * m) * 256 + jj] * kw_b[l + 32 * m];
            #pragma unroll
            for (int o = 16; o > 0; o >>= 1) up += __shfl_xor_sync(0xffffffffu, up, o);
            if (l == 0) g_u[jj] = up;
        }
    } else if (b == 128) {
        // w[e=t] and c
        float acc = 0.f;
        #pragma unroll 8
        for (int dd = 0; dd < 256; dd++)
            acc += kw_w[dd * 256 + t] * __ldg(&qw_b[dd]);
        g_w[t] = acc;
        if (t < 32) {
            float cp = 0.f;
            #pragma unroll
            for (int m = 0; m < 8; m++)
                cp += qw_b[t + 32 * m] * kw_b[t + 32 * m];
            #pragma unroll
            for (int o = 16; o > 0; o >>= 1) cp += __shfl_xor_sync(0xffffffffu, cp, o);
            if (t == 0) g_c = cp;
        }
    } else if (b == 129) {
        // mask dtype detection
        __shared__ int nf[2];
        if (t < 2) nf[t] = 0;
        __syncthreads();
        const unsigned* mw = (const unsigned*)maskp;
        int bad0 = 0, bad1 = 0;
        for (int i = t; i < 16384; i += 256) {   // 64KB, safe in all interpretations
            unsigned w = mw[i];
            if (w > 1u) bad0 = 1;
            if (w != 0u && w != 0x3F800000u) bad1 = 1;
        }
        if (bad0) nf[0] = 1;
        if (bad1) nf[1] = 1;
        __syncthreads();
        if (t == 0) g_mask_mode = nf[0] ? (nf[1] ? 0 : 2) : 1;
    } else {
        // WvT transpose: 64 blocks of 32x32 tiles
        __shared__ float s[32][33];
        const int bb = b - 130;
        const int di = (bb >> 3) * 32, jj = (bb & 7) * 32;
        const int tx = t & 31, ty = t >> 5;
        #pragma unroll
        for (int u2 = 0; u2 < 4; u2++)
            s[ty + 8 * u2][tx] = vw_w[(di + ty + 8 * u2) * 256 + (jj + tx)];
        __syncthreads();
        #pragma unroll
        for (int u2 = 0; u2 < 4; u2++)
            g_WvT[(jj + ty + 8 * u2) * 256 + (di + tx)] = s[tx][ty + 8 * u2];
    }
}

// ---------------- fused per-pair kernel ----------------
// smem (bytes):
//   [0,      68608)  kbf : 128 rows x stride-134 words; idx(e2)=e2+(e2>>5); overlays qT2
//                    qT2 : float2 (q[i][2d2],q[i][2d2+1]) at f2-index d2*16+i (phase 1 only)
//   [68608,  87072)  Qt  : float2 (Qt[i][e0],Qt[i][e1]) at f2 e2*18+(e2>>5)*2 + 8*ihalf + i
//   [87072,  88120)  ws2 : ull f32x2 at idx e2+(e2>>5)
//   [88120,  88184)  a_s : 16 floats
//   [88184,  89208)  ta_s: 256 floats
//   [89208,  89240)  red : 8 floats
#define SM_QTT 68608
#define SM_WS2 87072
#define SM_A   88120
#define SM_TA  88184
#define SM_RED 89208
#define SM_TOT 89240
#define KSTR   134

__device__ __forceinline__ float bsum(float v, float* red, int t) {
    __syncthreads();
    #pragma unroll
    for (int o = 16; o > 0; o >>= 1) v += __shfl_xor_sync(0xffffffffu, v, o);
    if ((t & 31) == 0) red[t >> 5] = v;
    __syncthreads();
    float r = red[0];
    #pragma unroll
    for (int i = 1; i < 8; i++) r += red[i];
    return r;
}
__device__ __forceinline__ float bmax(float v, float* red, int t) {
    __syncthreads();
    #pragma unroll
    for (int o = 16; o > 0; o >>= 1) v = fmaxf(v, __shfl_xor_sync(0xffffffffu, v, o));
    if ((t & 31) == 0) red[t >> 5] = v;
    __syncthreads();
    float r = red[0];
    #pragma unroll
    for (int i = 1; i < 8; i++) r = fmaxf(r, red[i]);
    return r;
}

__global__ void __launch_bounds__(256, 2)
fused_kernel(const float* __restrict__ q, const float* __restrict__ k,
             const float* __restrict__ v, const void* __restrict__ maskp)
{
    extern __shared__ unsigned char sm[];
    unsigned* kbf   = (unsigned*)sm;
    float2*   qT2f  = (float2*)sm;                 // overlay, phase-1 only
    float2*   Qtf   = (float2*)(sm + SM_QTT);
    ull*      ws2   = (ull*)(sm + SM_WS2);
    float*    a_s   = (float*)(sm + SM_A);
    float*    ta_s  = (float*)(sm + SM_TA);
    float*    red_s = (float*)(sm + SM_RED);

    const int pair = blockIdx.x;
    const int t = threadIdx.x;
    const float* qb = q + (size_t)pair * QL * DD;
    const float* kb = k + (size_t)pair * 256 * DD;
    const float* vb = v + (size_t)pair * 256 * DD;

    // ---- stage qT2 (d-pair f32x2, transposed) + ws2 ----
    {
        const float4* qs = (const float4*)qb;   // 1024 float4
        #pragma unroll
        for (int it = 0; it < 4; it++) {
            int idx = it * 256 + t;
            float4 f = qs[idx];
            int i = idx >> 6;
            int d0 = (idx & 63) * 4;
            qT2f[(d0 >> 1) * 16 + i]       = make_float2(f.x, f.y);
            qT2f[((d0 >> 1) + 1) * 16 + i] = make_float2(f.z, f.w);
        }
        if (t < 128) {
            float2 wv = *(const float2*)&g_w[2 * t];
            ws2[t + (t >> 5)] = pack2(wv.x, wv.y);
        }
    }
    __syncthreads();

    // ---- Phase 1: Qt[i][e] = sum_d q[i][d]*A[d][e], f32x2 over d-pairs ----
    {
        const int p = t & 127;        // e-pair index
        const int ihalf = t >> 7;     // 8 i's each
        ull acc0[8], acc1[8];
        #pragma unroll
        for (int i = 0; i < 8; i++) { acc0[i] = 0ull; acc1[i] = 0ull; }
        const uint2* A2 = (const uint2*)g_Au;   // index d2*128 + p
        #pragma unroll 2
        for (int d2 = 0; d2 < 128; d2++) {
            uint2 a = A2[d2 * 128 + p];
            ull Ae0 = bf2w(a.x);
            ull Ae1 = bf2w(a.y);
            const ulonglong2* qp = (const ulonglong2*)(qT2f + d2 * 16 + ihalf * 8);
            ulonglong2 qA = qp[0], qB = qp[1], qC = qp[2], qD = qp[3];
            FFMA2(acc0[0], qA.x, Ae0); FFMA2(acc1[0], qA.x, Ae1);
            FFMA2(acc0[1], qA.y, Ae0); FFMA2(acc1[1], qA.y, Ae1);
            FFMA2(acc0[2], qB.x, Ae0); FFMA2(acc1[2], qB.x, Ae1);
            FFMA2(acc0[3], qB.y, Ae0); FFMA2(acc1[3], qB.y, Ae1);
            FFMA2(acc0[4], qC.x, Ae0); FFMA2(acc1[4], qC.x, Ae1);
            FFMA2(acc0[5], qC.y, Ae0); FFMA2(acc1[5], qC.y, Ae1);
            FFMA2(acc0[6], qD.x, Ae0); FFMA2(acc1[6], qD.x, Ae1);
            FFMA2(acc0[7], qD.y, Ae0); FFMA2(acc1[7], qD.y, Ae1);
        }
        const int base = p * 18 + (p >> 5) * 2;   // f2 units; matches phase-2 reads
        #pragma unroll
        for (int i = 0; i < 8; i++) {
            float2 e0f = unpack2(acc0[i]);
            float2 e1f = unpack2(acc1[i]);
            Qtf[base + 8 * ihalf + i] = make_float2(e0f.x + e0f.y, e1f.x + e1f.y);
        }
    }
    // ---- a_i = q_i . u + c  (warp 0, from GLOBAL q: no smem conflicts) ----
    if (t < 32) {
        const float cc = g_c;
        for (int i = 0; i < QL; i++) {
            float p = 0.f;
            #pragma unroll
            for (int m = 0; m < 8; m++) {
                int dd = t + 32 * m;
                p += __ldg(&qb[i * 256 + dd]) * g_u[dd];
            }
            #pragma unroll
            for (int o = 16; o > 0; o >>= 1) p += __shfl_xor_sync(0xffffffffu, p, o);
            if (t == 0) a_s[i] = p + cc;
        }
    }

    // ---- Phase 2: register-tiled scores. Thread = (g=t>>3: 4 rows, ih=(t>>2)&1: 8 i's,
    //      q4=t&3: 64 e's).  Two 128-row k tiles. ----
    const int q4 = t & 3;
    const int ih = (t >> 2) & 1;
    const int g  = t >> 3;
    for (int tile = 0; tile < 2; tile++) {
        __syncthreads();          // kbf region free (phase1 qT2 reads done / prev tile done)
        {   // stage k tile as bf16, conflict-free stores
            const float4* ks = (const float4*)(kb + tile * 128 * 256);
            #pragma unroll 4
            for (int it = 0; it < 32; it++) {
                int idx = it * 256 + t;     // 8192 float4
                float4 f = ks[idx];
                int row = idx >> 6;
                int e2a = (idx & 63) * 2;
                int off = row * KSTR + e2a + (e2a >> 5);
                kbf[off]     = f2bf(f.x, f.y);
                kbf[off + 1] = f2bf(f.z, f.w);
            }
        }
        __syncthreads();
        const unsigned* kbase = kbf + (4 * g) * KSTR + 33 * q4;
        const ull*      wbase = ws2 + 33 * q4;
        const float2*   Qbase = Qtf + 578 * q4 + 8 * ih;
        ull acc[32];              // [rr*8 + ii]
        #pragma unroll
        for (int i = 0; i < 32; i++) acc[i] = 0ull;
        ull wk[4];
        #pragma unroll
        for (int i = 0; i < 4; i++) wk[i] = 0ull;
        #pragma unroll 2
        for (int j = 0; j < 32; j++) {
            ull k2[4];
            k2[0] = bf2w(kbase[j]);
            k2[1] = bf2w(kbase[j + KSTR]);
            k2[2] = bf2w(kbase[j + 2 * KSTR]);
            k2[3] = bf2w(kbase[j + 3 * KSTR]);
            ull w2 = wbase[j];
            const ulonglong2* Qp = (const ulonglong2*)(Qbase + 18 * j);
            ulonglong2 qA = Qp[0], qB = Qp[1], qC = Qp[2], qD = Qp[3];
            #pragma unroll
            for (int rr = 0; rr < 4; rr++) {
                FFMA2(wk[rr], w2, k2[rr]);
                FFMA2(acc[rr * 8 + 0], qA.x, k2[rr]);
                FFMA2(acc[rr * 8 + 1], qA.y, k2[rr]);
                FFMA2(acc[rr * 8 + 2], qB.x, k2[rr]);
                FFMA2(acc[rr * 8 + 3], qB.y, k2[rr]);
                FFMA2(acc[rr * 8 + 4], qC.x, k2[rr]);
                FFMA2(acc[rr * 8 + 5], qC.y, k2[rr]);
                FFMA2(acc[rr * 8 + 6], qD.x, k2[rr]);
                FFMA2(acc[rr * 8 + 7], qD.y, k2[rr]);
            }
        }
        // collapse f32x2, butterfly over e-quarters (lane bits 0,1)
        float sc[32], wks[4];
        #pragma unroll
        for (int i = 0; i < 32; i++) {
            float2 f = unpack2(acc[i]);
            float s = f.x + f.y;
            s += __shfl_xor_sync(0xffffffffu, s, 1);
            s += __shfl_xor_sync(0xffffffffu, s, 2);
            sc[i] = s;
        }
        #pragma unroll
        for (int rr = 0; rr < 4; rr++) {
            float2 f = unpack2(wk[rr]);
            float s = f.x + f.y;
            s += __shfl_xor_sync(0xffffffffu, s, 1);
            s += __shfl_xor_sync(0xffffffffu, s, 2);
            wks[rr] = s;
        }
        float av[8];
        #pragma unroll
        for (int ii = 0; ii < 8; ii++) av[ii] = a_s[8 * ih + ii];
        #pragma unroll
        for (int rr = 0; rr < 4; rr++) {
            float m = -1e30f;
            #pragma unroll
            for (int ii = 0; ii < 8; ii++) m = fmaxf(m, sc[rr * 8 + ii] + av[ii]);
            m = fmaxf(m, __shfl_xor_sync(0xffffffffu, m, 4));   // combine i-halves
            if ((t & 7) == 0)
                ta_s[tile * 128 + 4 * g + rr] = wks[rr] + m;
        }
    }

    // ---- Phase 3: normalize, mask, softmax ----
    float cnt;
    {
        __syncthreads();
        float tv = ta_s[t];
        float ss = bsum(tv * tv, red_s, t);
        float inv = rsqrtf(ss);
        const int mm = g_mask_mode;
        bool masked;
        size_t mi = (size_t)pair * 256 + t;
        if (mm == 0)      masked = ((const unsigned char*)maskp)[mi] != 0;
        else if (mm == 1) masked = ((const int*)maskp)[mi] != 0;
        else              masked = ((const float*)maskp)[mi] != 0.f;
        float x = masked ? -10.f : tv * inv;
        cnt = bsum(masked ? 0.f : 1.f, red_s, t);
        float mx = bmax(x, red_s, t);
        float ex = __expf(x - mx);
        float se = bsum(ex, red_s, t);
        float attn = (cnt == 0.f) ? 0.f : ex / se;
        ta_s[t] = attn;
        __syncthreads();
    }

    // ---- Phase 4: tvec[j=t] = sum_v attn[v] * v[v][t] ----
    {
        float acc = 0.f;
        #pragma unroll 16
        for (int vv = 0; vv < 256; vv++)
            acc += ta_s[vv] * vb[vv * 256 + t];
        g_tvec[pair * 256 + t] = acc;
        if (t == 0) g_sA[pair] = (cnt > 0.f) ? 1.f : 0.f;
    }
}

// ---------------- output projection: OUT = TVEC @ WvT + sA*vb ----------------
__global__ void out_kernel(const float* __restrict__ vw_b, float* __restrict__ out)
{
    __shared__ float tvT[256 * 20];
    __shared__ float sA_s[16];
    __shared__ float vb_s[256];
    const int t = threadIdx.x;
    const int p0 = blockIdx.x * 16;
    vb_s[t] = vw_b[t];
    if (t < 16) sA_s[t] = g_sA[p0 + t];
    #pragma unroll
    for (int it = 0; it < 16; it++) {
        int idx = it * 256 + t;
        int r = idx >> 8, j = idx & 255;
        tvT[j * 20 + r] = g_tvec[(p0 + r) * 256 + j];
    }
    __syncthreads();
    float acc[16];
    #pragma unroll
    for (int r = 0; r < 16; r++) acc[r] = 0.f;
    #pragma unroll 4
    for (int j = 0; j < 256; j++) {
        float wv = g_WvT[j * 256 + t];
        const float4* T = (const float4*)&tvT[j * 20];
        float4 t0 = T[0], t1 = T[1], t2 = T[2], t3 = T[3];
        acc[0]  += t0.x * wv;  acc[1]  += t0.y * wv;
        acc[2]  += t0.z * wv;  acc[3]  += t0.w * wv;
        acc[4]  += t1.x * wv;  acc[5]  += t1.y * wv;
        acc[6]  += t1.z * wv;  acc[7]  += t1.w * wv;
        acc[8]  += t2.x * wv;  acc[9]  += t2.y * wv;
        acc[10] += t2.z * wv;  acc[11] += t2.w * wv;
        acc[12] += t3.x * wv;  acc[13] += t3.y * wv;
        acc[14] += t3.z * wv;  acc[15] += t3.w * wv;
    }
    #pragma unroll
    for (int r = 0; r < 16; r++)
        out[(size_t)(p0 + r) * 256 + t] = acc[r] + sA_s[r] * vb_s[t];
}

extern "C" void kernel_launch(void* const* d_in, const int* in_sizes, int n_in,
                              void* d_out, int out_size)
{
    const float* q    = (const float*)d_in[0];
    const float* k    = (const float*)d_in[1];
    const float* v    = (const float*)d_in[2];
    const void*  m    = d_in[3];
    const float* qw_w = (const float*)d_in[4];
    const float* qw_b = (const float*)d_in[5];
    const float* kw_w = (const float*)d_in[6];
    const float* kw_b = (const float*)d_in[7];
    const float* vw_w = (const float*)d_in[8];
    const float* vw_b = (const float*)d_in[9];
    float* out = (float*)d_out;
    (void)in_sizes; (void)n_in; (void)out_size;

    cudaFuncSetAttribute(fused_kernel, cudaFuncAttributeMaxDynamicSharedMemorySize, SM_TOT);

    setup_kernel<<<194, 256>>>(qw_w, qw_b, kw_w, kw_b, vw_w, m);
    fused_kernel<<<PAIRS, 256, SM_TOT>>>(q, k, v, m);
    out_kernel<<<64, 256>>>(vw_b, out);
}

// round 6
// speedup vs baseline: 1.4744x; 1.1408x over previous
#include <cuda_runtime.h>
#include <cuda_bf16.h>
#include <cstdint>

typedef unsigned long long ull;

#define PAIRS 1024
#define DD 256
#define QL 16

// ---------------- persistent scratch / precomputed ----------------
__device__ unsigned g_Au[128 * 256];       // bf16x2( A[2*d2][e], A[2*d2+1][e] ) at [d2*256+e]
__device__ float    g_WvT[256 * 256];      // WvT[j][d] = vw_w[d][j]
__device__ float    g_u[256];
__device__ float    g_w[256];
__device__ float    g_c;
__device__ int      g_mask_mode;           // 0=u8 bool, 1=int32, 2=float32
__device__ float    g_tvec[PAIRS * 256];   // attn . v  per pair
__device__ float    g_sA[PAIRS];           // 1 if any unmasked else 0

__device__ __forceinline__ unsigned f2bf(float a, float b) {
    __nv_bfloat162 h = __floats2bfloat162_rn(a, b);
    return *reinterpret_cast<unsigned*>(&h);
}
__device__ __forceinline__ ull pack2(float a, float b) {
    ull r; asm("mov.b64 %0, {%1,%2};" : "=l"(r) : "f"(a), "f"(b)); return r;
}
__device__ __forceinline__ float2 unpack2(ull v) {
    float2 f; asm("mov.b64 {%0,%1}, %2;" : "=f"(f.x), "=f"(f.y) : "l"(v)); return f;
}
// bf16x2 (lo,hi) -> f32x2 (lo,hi)
__device__ __forceinline__ ull bf2w(unsigned u) {
    return pack2(__uint_as_float(u << 16), __uint_as_float(u & 0xFFFF0000u));
}
#define FFMA2(d, a, b) asm("fma.rn.f32x2 %0, %1, %2, %0;" : "+l"(d) : "l"(a), "l"(b))

// ---------------- setup kernel (MLP-first rewrite) ----------------
__global__ void setup_kernel(const float* __restrict__ qw_w, const float* __restrict__ qw_b,
                             const float* __restrict__ kw_w, const float* __restrict__ kw_b,
                             const float* __restrict__ vw_w, const void* __restrict__ maskp)
{
    const int b = blockIdx.x;
    const int t = threadIdx.x;
    if (b < 128) {
        // A rows j0=2b, 2b+1 (col e=t), packed bf16x2; plus u[2b], u[2b+1]
        const int j0 = 2 * b;
        float a0 = 0.f, a1 = 0.f;
        for (int db = 0; db < 256; db += 8) {
            float kv[8]; float2 qv[8];
            #pragma unroll
            for (int m = 0; m < 8; m++) kv[m] = kw_w[(db + m) * 256 + t];
            #pragma unroll
            for (int m = 0; m < 8; m++) qv[m] = *(const float2*)&qw_w[(db + m) * 256 + j0];
            #pragma unroll
            for (int m = 0; m < 8; m++) { a0 += qv[m].x * kv[m]; a1 += qv[m].y * kv[m]; }
        }
        g_Au[b * 256 + t] = f2bf(a0, a1);
        if (t < 64) {
            const int jj = j0 + (t >> 5);
            const int l = t & 31;
            float up = 0.f;
            #pragma unroll
            for (int m = 0; m < 8; m++)
                up += qw_w[(l + 32 * m) * 256 + jj] * kw_b[l + 32 * m];
            #pragma unroll
            for (int o = 16; o > 0; o >>= 1) up += __shfl_xor_sync(0xffffffffu, up, o);
            if (l == 0) g_u[jj] = up;
        }
    } else if (b == 128) {
        // w[e=t] and c
        float acc = 0.f;
        for (int db = 0; db < 256; db += 8) {
            float kv[8]; float qb2[8];
            #pragma unroll
            for (int m = 0; m < 8; m++) kv[m] = kw_w[(db + m) * 256 + t];
            #pragma unroll
            for (int m = 0; m < 8; m++) qb2[m] = __ldg(&qw_b[db + m]);
            #pragma unroll
            for (int m = 0; m < 8; m++) acc += kv[m] * qb2[m];
        }
        g_w[t] = acc;
        if (t < 32) {
            float cp = 0.f;
            #pragma unroll
            for (int m = 0; m < 8; m++)
                cp += qw_b[t + 32 * m] * kw_b[t + 32 * m];
            #pragma unroll
            for (int o = 16; o > 0; o >>= 1) cp += __shfl_xor_sync(0xffffffffu, cp, o);
            if (t == 0) g_c = cp;
        }
    } else if (b == 129) {
        // mask dtype detection
        __shared__ int nf[2];
        if (t < 2) nf[t] = 0;
        __syncthreads();
        const unsigned* mw = (const unsigned*)maskp;
        int bad0 = 0, bad1 = 0;
        for (int i = t; i < 16384; i += 256) {   // 64KB, safe in all interpretations
            unsigned w = mw[i];
            if (w > 1u) bad0 = 1;
            if (w != 0u && w != 0x3F800000u) bad1 = 1;
        }
        if (bad0) nf[0] = 1;
        if (bad1) nf[1] = 1;
        __syncthreads();
        if (t == 0) g_mask_mode = nf[0] ? (nf[1] ? 0 : 2) : 1;
    } else {
        // WvT transpose: 64 blocks of 32x32 tiles
        __shared__ float s[32][33];
        const int bb = b - 130;
        const int di = (bb >> 3) * 32, jj = (bb & 7) * 32;
        const int tx = t & 31, ty = t >> 5;
        #pragma unroll
        for (int u2 = 0; u2 < 4; u2++)
            s[ty + 8 * u2][tx] = vw_w[(di + ty + 8 * u2) * 256 + (jj + tx)];
        __syncthreads();
        #pragma unroll
        for (int u2 = 0; u2 < 4; u2++)
            g_WvT[(jj + ty + 8 * u2) * 256 + (di + tx)] = s[tx][ty + 8 * u2];
    }
}

// ---------------- fused per-pair kernel ----------------
// smem (bytes):
//   [0,      68608)  kbf : 128 rows x stride-134 words; idx(e2)=e2+(e2>>5); overlays qT2
//                    qT2 : float2 (q[i][2d2],q[i][2d2+1]) at f2-index d2*16+i (phase 1 only)
//   [68608,  87072)  Qt  : float2 (Qt[i][e0],Qt[i][e1]) at f2 e2*18+(e2>>5)*2 + i (i=0..15)
//   [87072,  88120)  ws2 : ull f32x2 at idx e2+(e2>>5)
//   [88120,  88184)  a_s : 16 floats
//   [88184,  89208)  ta_s: 256 floats
//   [89208,  89240)  red : 8 floats
#define SM_QTT 68608
#define SM_WS2 87072
#define SM_A   88120
#define SM_TA  88184
#define SM_RED 89208
#define SM_TOT 89240
#define KSTR   134

__device__ __forceinline__ float bsum(float v, float* red, int t) {
    __syncthreads();
    #pragma unroll
    for (int o = 16; o > 0; o >>= 1) v += __shfl_xor_sync(0xffffffffu, v, o);
    if ((t & 31) == 0) red[t >> 5] = v;
    __syncthreads();
    float r = red[0];
    #pragma unroll
    for (int i = 1; i < 8; i++) r += red[i];
    return r;
}
__device__ __forceinline__ float bmax(float v, float* red, int t) {
    __syncthreads();
    #pragma unroll
    for (int o = 16; o > 0; o >>= 1) v = fmaxf(v, __shfl_xor_sync(0xffffffffu, v, o));
    if ((t & 31) == 0) red[t >> 5] = v;
    __syncthreads();
    float r = red[0];
    #pragma unroll
    for (int i = 1; i < 8; i++) r = fmaxf(r, red[i]);
    return r;
}

__global__ void __launch_bounds__(256, 2)
fused_kernel(const float* __restrict__ q, const float* __restrict__ k,
             const float* __restrict__ v, const void* __restrict__ maskp)
{
    extern __shared__ unsigned char sm[];
    unsigned* kbf   = (unsigned*)sm;
    float2*   qT2f  = (float2*)sm;                 // overlay, phase-1 only
    float2*   Qtf   = (float2*)(sm + SM_QTT);
    ull*      ws2   = (ull*)(sm + SM_WS2);
    float*    a_s   = (float*)(sm + SM_A);
    float*    ta_s  = (float*)(sm + SM_TA);
    float*    red_s = (float*)(sm + SM_RED);

    const int pair = blockIdx.x;
    const int t = threadIdx.x;
    const float* qb = q + (size_t)pair * QL * DD;
    const float* kb = k + (size_t)pair * 256 * DD;
    const float* vb = v + (size_t)pair * 256 * DD;

    // ---- stage qT2 (d-pair f32x2, transposed) + ws2 ----
    {
        const float4* qs = (const float4*)qb;   // 1024 float4
        #pragma unroll
        for (int it = 0; it < 4; it++) {
            int idx = it * 256 + t;
            float4 f = qs[idx];
            int i = idx >> 6;
            int d0 = (idx & 63) * 4;
            qT2f[(d0 >> 1) * 16 + i]       = make_float2(f.x, f.y);
            qT2f[((d0 >> 1) + 1) * 16 + i] = make_float2(f.z, f.w);
        }
        if (t < 128) {
            float2 wv = *(const float2*)&g_w[2 * t];
            ws2[t + (t >> 5)] = pack2(wv.x, wv.y);
        }
    }
    __syncthreads();

    // ---- Phase 1: Qt[i][e] = sum_d q[i][d]*A[d][e], f32x2 over d-pairs, MLP 8 ----
    {
        const int p = t & 127;        // e-pair index
        const int ihalf = t >> 7;     // 8 i's each
        ull acc0[8], acc1[8];
        #pragma unroll
        for (int i = 0; i < 8; i++) { acc0[i] = 0ull; acc1[i] = 0ull; }
        const uint2* A2 = (const uint2*)g_Au;   // index d2*128 + p
        #pragma unroll 8
        for (int d2 = 0; d2 < 128; d2++) {
            uint2 a = A2[d2 * 128 + p];
            ull Ae0 = bf2w(a.x);
            ull Ae1 = bf2w(a.y);
            const ulonglong2* qp = (const ulonglong2*)(qT2f + d2 * 16 + ihalf * 8);
            ulonglong2 qA = qp[0], qB = qp[1], qC = qp[2], qD = qp[3];
            FFMA2(acc0[0], qA.x, Ae0); FFMA2(acc1[0], qA.x, Ae1);
            FFMA2(acc0[1], qA.y, Ae0); FFMA2(acc1[1], qA.y, Ae1);
            FFMA2(acc0[2], qB.x, Ae0); FFMA2(acc1[2], qB.x, Ae1);
            FFMA2(acc0[3], qB.y, Ae0); FFMA2(acc1[3], qB.y, Ae1);
            FFMA2(acc0[4], qC.x, Ae0); FFMA2(acc1[4], qC.x, Ae1);
            FFMA2(acc0[5], qC.y, Ae0); FFMA2(acc1[5], qC.y, Ae1);
            FFMA2(acc0[6], qD.x, Ae0); FFMA2(acc1[6], qD.x, Ae1);
            FFMA2(acc0[7], qD.y, Ae0); FFMA2(acc1[7], qD.y, Ae1);
        }
        const int base = p * 18 + (p >> 5) * 2;   // f2 units
        #pragma unroll
        for (int i = 0; i < 8; i++) {
            float2 e0f = unpack2(acc0[i]);
            float2 e1f = unpack2(acc1[i]);
            Qtf[base + 8 * ihalf + i] = make_float2(e0f.x + e0f.y, e1f.x + e1f.y);
        }
    }
    // ---- a_i = q_i . u + c  (warp 0, from GLOBAL q) ----
    if (t < 32) {
        const float cc = g_c;
        for (int i = 0; i < QL; i++) {
            float p = 0.f;
            #pragma unroll
            for (int m = 0; m < 8; m++) {
                int dd = t + 32 * m;
                p += __ldg(&qb[i * 256 + dd]) * g_u[dd];
            }
            #pragma unroll
            for (int o = 16; o > 0; o >>= 1) p += __shfl_xor_sync(0xffffffffu, p, o);
            if (t == 0) a_s[i] = p + cc;
        }
    }

    // ---- Phase 2: register-tiled scores.
    //      Thread = (eh=t&1: e-half, iq=(t>>1)&3: 4 i's, g=t>>3: 4 k-rows). 16 acc.
    const int eh = t & 1;
    const int iq = (t >> 1) & 3;
    const int g  = t >> 3;
    for (int tile = 0; tile < 2; tile++) {
        __syncthreads();          // kbf region free
        {   // stage k tile as bf16, conflict-free stores
            const float4* ks = (const float4*)(kb + tile * 128 * 256);
            #pragma unroll 4
            for (int it = 0; it < 32; it++) {
                int idx = it * 256 + t;     // 8192 float4
                float4 f = ks[idx];
                int row = idx >> 6;
                int e2a = (idx & 63) * 2;
                int off = row * KSTR + e2a + (e2a >> 5);
                kbf[off]     = f2bf(f.x, f.y);
                kbf[off + 1] = f2bf(f.z, f.w);
            }
        }
        __syncthreads();
        const unsigned* kbase = kbf + (4 * g) * KSTR + 66 * eh;
        const ull*      wbase = ws2 + 66 * eh;
        const float2*   Qbase = Qtf + 1156 * eh + 4 * iq;
        ull acc[16];              // [rr*4 + ii]
        #pragma unroll
        for (int i = 0; i < 16; i++) acc[i] = 0ull;
        ull wk[4];
        #pragma unroll
        for (int i = 0; i < 4; i++) wk[i] = 0ull;
        #pragma unroll 4
        for (int j = 0; j < 64; j++) {
            int jj = j + (j >> 5);
            ull k2[4];
            k2[0] = bf2w(kbase[jj]);
            k2[1] = bf2w(kbase[jj + KSTR]);
            k2[2] = bf2w(kbase[jj + 2 * KSTR]);
            k2[3] = bf2w(kbase[jj + 3 * KSTR]);
            ull w2 = wbase[jj];
            const ulonglong2* Qp = (const ulonglong2*)(Qbase + 18 * j + 2 * (j >> 5));
            ulonglong2 qA = Qp[0], qB = Qp[1];
            #pragma unroll
            for (int rr = 0; rr < 4; rr++) {
                FFMA2(wk[rr], w2, k2[rr]);
                FFMA2(acc[rr * 4 + 0], qA.x, k2[rr]);
                FFMA2(acc[rr * 4 + 1], qA.y, k2[rr]);
                FFMA2(acc[rr * 4 + 2], qB.x, k2[rr]);
                FFMA2(acc[rr * 4 + 3], qB.y, k2[rr]);
            }
        }
        // collapse f32x2, combine e-halves (lane bit 0)
        float sc[16], wks[4];
        #pragma unroll
        for (int i = 0; i < 16; i++) {
            float2 f = unpack2(acc[i]);
            float s = f.x + f.y;
            s += __shfl_xor_sync(0xffffffffu, s, 1);
            sc[i] = s;
        }
        #pragma unroll
        for (int rr = 0; rr < 4; rr++) {
            float2 f = unpack2(wk[rr]);
            float s = f.x + f.y;
            s += __shfl_xor_sync(0xffffffffu, s, 1);
            wks[rr] = s;
        }
        float av[4];
        #pragma unroll
        for (int ii = 0; ii < 4; ii++) av[ii] = a_s[4 * iq + ii];
        #pragma unroll
        for (int rr = 0; rr < 4; rr++) {
            float m = -1e30f;
            #pragma unroll
            for (int ii = 0; ii < 4; ii++) m = fmaxf(m, sc[rr * 4 + ii] + av[ii]);
            m = fmaxf(m, __shfl_xor_sync(0xffffffffu, m, 2));   // iq bit 0
            m = fmaxf(m, __shfl_xor_sync(0xffffffffu, m, 4));   // iq bit 1
            if ((t & 7) == 0)
                ta_s[tile * 128 + 4 * g + rr] = wks[rr] + m;
        }
    }

    // ---- Phase 3: normalize, mask, softmax ----
    float cnt;
    {
        __syncthreads();
        float tv = ta_s[t];
        float ss = bsum(tv * tv, red_s, t);
        float inv = rsqrtf(ss);
        const int mm = g_mask_mode;
        bool masked;
        size_t mi = (size_t)pair * 256 + t;
        if (mm == 0)      masked = ((const unsigned char*)maskp)[mi] != 0;
        else if (mm == 1) masked = ((const int*)maskp)[mi] != 0;
        else              masked = ((const float*)maskp)[mi] != 0.f;
        float x = masked ? -10.f : tv * inv;
        cnt = bsum(masked ? 0.f : 1.f, red_s, t);
        float mx = bmax(x, red_s, t);
        float ex = __expf(x - mx);
        float se = bsum(ex, red_s, t);
        float attn = (cnt == 0.f) ? 0.f : ex / se;
        ta_s[t] = attn;
        __syncthreads();
    }

    // ---- Phase 4: tvec[j=t] = sum_v attn[v] * v[v][t] ----
    {
        float acc = 0.f;
        #pragma unroll 16
        for (int vv = 0; vv < 256; vv++)
            acc += ta_s[vv] * vb[vv * 256 + t];
        g_tvec[pair * 256 + t] = acc;
        if (t == 0) g_sA[pair] = (cnt > 0.f) ? 1.f : 0.f;
    }
}

// ---------------- output projection: OUT = TVEC @ WvT + sA*vb ----------------
__global__ void out_kernel(const float* __restrict__ vw_b, float* __restrict__ out)
{
    __shared__ float tvT[256 * 20];
    __shared__ float sA_s[16];
    __shared__ float vb_s[256];
    const int t = threadIdx.x;
    const int p0 = blockIdx.x * 16;
    vb_s[t] = vw_b[t];
    if (t < 16) sA_s[t] = g_sA[p0 + t];
    #pragma unroll
    for (int it = 0; it < 16; it++) {
        int idx = it * 256 + t;
        int r = idx >> 8, j = idx & 255;
        tvT[j * 20 + r] = g_tvec[(p0 + r) * 256 + j];
    }
    __syncthreads();
    float acc[16];
    #pragma unroll
    for (int r = 0; r < 16; r++) acc[r] = 0.f;
    #pragma unroll 4
    for (int j = 0; j < 256; j++) {
        float wv = g_WvT[j * 256 + t];
        const float4* T = (const float4*)&tvT[j * 20];
        float4 t0 = T[0], t1 = T[1], t2 = T[2], t3 = T[3];
        acc[0]  += t0.x * wv;  acc[1]  += t0.y * wv;
        acc[2]  += t0.z * wv;  acc[3]  += t0.w * wv;
        acc[4]  += t1.x * wv;  acc[5]  += t1.y * wv;
        acc[6]  += t1.z * wv;  acc[7]  += t1.w * wv;
        acc[8]  += t2.x * wv;  acc[9]  += t2.y * wv;
        acc[10] += t2.z * wv;  acc[11] += t2.w * wv;
        acc[12] += t3.x * wv;  acc[13] += t3.y * wv;
        acc[14] += t3.z * wv;  acc[15] += t3.w * wv;
    }
    #pragma unroll
    for (int r = 0; r < 16; r++)
        out[(size_t)(p0 + r) * 256 + t] = acc[r] + sA_s[r] * vb_s[t];
}

extern "C" void kernel_launch(void* const* d_in, const int* in_sizes, int n_in,
                              void* d_out, int out_size)
{
    const float* q    = (const float*)d_in[0];
    const float* k    = (const float*)d_in[1];
    const float* v    = (const float*)d_in[2];
    const void*  m    = d_in[3];
    const float* qw_w = (const float*)d_in[4];
    const float* qw_b = (const float*)d_in[5];
    const float* kw_w = (const float*)d_in[6];
    const float* kw_b = (const float*)d_in[7];
    const float* vw_w = (const float*)d_in[8];
    const float* vw_b = (const float*)d_in[9];
    float* out = (float*)d_out;
    (void)in_sizes; (void)n_in; (void)out_size;

    cudaFuncSetAttribute(fused_kernel, cudaFuncAttributeMaxDynamicSharedMemorySize, SM_TOT);

    setup_kernel<<<194, 256>>>(qw_w, qw_b, kw_w, kw_b, vw_w, m);
    fused_kernel<<<PAIRS, 256, SM_TOT>>>(q, k, v, m);
    out_kernel<<<64, 256>>>(vw_b, out);
}

// round 7
// speedup vs baseline: 1.4834x; 1.0060x over previous
#include <cuda_runtime.h>
#include <cuda_bf16.h>
#include <cstdint>

typedef unsigned long long ull;

#define PAIRS 1024
#define DD 256
#define QL 16

// ---------------- persistent scratch / precomputed ----------------
__device__ unsigned g_Au[128 * 256];       // bf16x2( A[2*d2][e], A[2*d2+1][e] ) at [d2*256+e]
__device__ float    g_WvT[256 * 256];      // WvT[j][d] = vw_w[d][j]
__device__ float    g_u[256];
__device__ float    g_w[256];
__device__ float    g_c;
__device__ int      g_mask_mode;           // 0=u8 bool, 1=int32, 2=float32
__device__ float    g_tvec[PAIRS * 256];   // attn . v  per pair
__device__ float    g_sA[PAIRS];           // 1 if any unmasked else 0

__device__ __forceinline__ unsigned f2bf(float a, float b) {
    __nv_bfloat162 h = __floats2bfloat162_rn(a, b);
    return *reinterpret_cast<unsigned*>(&h);
}
__device__ __forceinline__ ull pack2(float a, float b) {
    ull r; asm("mov.b64 %0, {%1,%2};" : "=l"(r) : "f"(a), "f"(b)); return r;
}
__device__ __forceinline__ float2 unpack2(ull v) {
    float2 f; asm("mov.b64 {%0,%1}, %2;" : "=f"(f.x), "=f"(f.y) : "l"(v)); return f;
}
__device__ __forceinline__ ull bf2w(unsigned u) {
    return pack2(__uint_as_float(u << 16), __uint_as_float(u & 0xFFFF0000u));
}
#define FFMA2(d, a, b) asm("fma.rn.f32x2 %0, %1, %2, %0;" : "+l"(d) : "l"(a), "l"(b))
#define BARX(id) asm volatile("bar.sync %0, 256;" :: "r"(id) : "memory")

// ---------------- setup kernel: tiled-GEMM A + parallel extras ----------------
__global__ void setup_kernel(const float* __restrict__ qw_w, const float* __restrict__ qw_b,
                             const float* __restrict__ kw_w, const float* __restrict__ kw_b,
                             const float* __restrict__ vw_w, const void* __restrict__ maskp)
{
    const int b = blockIdx.x;
    const int t = threadIdx.x;
    if (b < 64) {
        // A tile: e in [e0, e0+64), j in [j0, j0+16).  A[j][e] = sum_d qw[d][j]*kw[d][e]
        __shared__ float wq_s[256 * 16];
        const int e0 = (b & 3) * 64;
        const int j0 = (b >> 2) * 16;
        #pragma unroll
        for (int it = 0; it < 16; it++) {
            int lin = it * 256 + t;
            int d = lin >> 4, jj = lin & 15;
            wq_s[d * 16 + jj] = qw_w[d * 256 + j0 + jj];
        }
        __syncthreads();
        const int e = e0 + (t & 63);
        const int jg = t >> 6;
        ull acc2[2] = {0ull, 0ull};
        #pragma unroll 8
        for (int d = 0; d < 256; d++) {
            float kv = kw_w[d * 256 + e];
            ull kv2 = pack2(kv, kv);
            ulonglong2 wp = *(const ulonglong2*)(wq_s + d * 16 + jg * 4);
            FFMA2(acc2[0], wp.x, kv2);
            FFMA2(acc2[1], wp.y, kv2);
        }
        float2 f0 = unpack2(acc2[0]);
        float2 f1 = unpack2(acc2[1]);
        int jp = (j0 + jg * 4) >> 1;
        g_Au[jp * 256 + e]       = f2bf(f0.x, f0.y);
        g_Au[(jp + 1) * 256 + e] = f2bf(f1.x, f1.y);
    } else if (b == 64) {
        // u[j=t] = sum_d qw[d][j]*kw_b[d]
        float acc = 0.f;
        #pragma unroll 8
        for (int d = 0; d < 256; d++)
            acc += qw_w[d * 256 + t] * __ldg(&kw_b[d]);
        g_u[t] = acc;
    } else if (b == 65) {
        // w[e=t] = sum_d kw[d][e]*qw_b[d]
        float acc = 0.f;
        #pragma unroll 8
        for (int d = 0; d < 256; d++)
            acc += kw_w[d * 256 + t] * __ldg(&qw_b[d]);
        g_w[t] = acc;
    } else if (b == 66) {
        // c + mask dtype detection
        if (t < 32) {
            float cp = 0.f;
            #pragma unroll
            for (int m = 0; m < 8; m++)
                cp += qw_b[t + 32 * m] * kw_b[t + 32 * m];
            #pragma unroll
            for (int o = 16; o > 0; o >>= 1) cp += __shfl_xor_sync(0xffffffffu, cp, o);
            if (t == 0) g_c = cp;
        }
        __shared__ int nf[2];
        if (t < 2) nf[t] = 0;
        __syncthreads();
        const unsigned* mw = (const unsigned*)maskp;
        int bad0 = 0, bad1 = 0;
        for (int i = t; i < 16384; i += 256) {
            unsigned w = mw[i];
            if (w > 1u) bad0 = 1;
            if (w != 0u && w != 0x3F800000u) bad1 = 1;
        }
        if (bad0) nf[0] = 1;
        if (bad1) nf[1] = 1;
        __syncthreads();
        if (t == 0) g_mask_mode = nf[0] ? (nf[1] ? 0 : 2) : 1;
    } else {
        // WvT transpose: 64 blocks of 32x32 tiles
        __shared__ float s[32][33];
        const int bb = b - 67;
        const int di = (bb >> 3) * 32, jj = (bb & 7) * 32;
        const int tx = t & 31, ty = t >> 5;
        #pragma unroll
        for (int u2 = 0; u2 < 4; u2++)
            s[ty + 8 * u2][tx] = vw_w[(di + ty + 8 * u2) * 256 + (jj + tx)];
        __syncthreads();
        #pragma unroll
        for (int u2 = 0; u2 < 4; u2++)
            g_WvT[(jj + ty + 8 * u2) * 256 + (di + tx)] = s[tx][ty + 8 * u2];
    }
}

// ---------------- fused per-pair kernel (warp-specialized pipeline) ----------------
// smem (bytes):
//   [0,      35072)  kbuf0 : 64 rows x stride-137 words bf16x2; col idx(e2)=e2+(e2>>5)
//   [35072,  70144)  kbuf1
//   [70144,  86528)  qT2   : float2 (q[i][2d2],q[i][2d2+1]) at f2-index d2*16+i
//   [86528, 104992)  Qt    : float2 (Qt[i][e0],Qt[i][e1]) at f2 e2*18+(e2>>5)*2 + i
//   [104992,106016)  ws    : 128 ull f32x2 (w[2e2],w[2e2+1])
//   [106016,106080)  a_s   : 16 floats
//   [106080,107104)  ta_s  : 256 floats
//   [107104,107136)  red   : 8 floats
#define SM_KB1 35072
#define SM_QT2 70144
#define SM_QTT 86528
#define SM_WS  104992
#define SM_A   106016
#define SM_TA  106080
#define SM_RED 107104
#define SM_TOT 107136
#define KSTR   137

__device__ __forceinline__ float bsum(float v, float* red, int t) {
    __syncthreads();
    #pragma unroll
    for (int o = 16; o > 0; o >>= 1) v += __shfl_xor_sync(0xffffffffu, v, o);
    if ((t & 31) == 0) red[t >> 5] = v;
    __syncthreads();
    float r = red[0];
    #pragma unroll
    for (int i = 1; i < 8; i++) r += red[i];
    return r;
}
__device__ __forceinline__ float bmax(float v, float* red, int t) {
    __syncthreads();
    #pragma unroll
    for (int o = 16; o > 0; o >>= 1) v = fmaxf(v, __shfl_xor_sync(0xffffffffu, v, o));
    if ((t & 31) == 0) red[t >> 5] = v;
    __syncthreads();
    float r = red[0];
    #pragma unroll
    for (int i = 1; i < 8; i++) r = fmaxf(r, red[i]);
    return r;
}

__global__ void __launch_bounds__(256, 2)
fused_kernel(const float* __restrict__ q, const float* __restrict__ k,
             const float* __restrict__ v, const void* __restrict__ maskp)
{
    extern __shared__ unsigned char sm[];
    unsigned* kbuf[2];
    kbuf[0] = (unsigned*)sm;
    kbuf[1] = (unsigned*)(sm + SM_KB1);
    float2*   qT2f  = (float2*)(sm + SM_QT2);
    float2*   Qtf   = (float2*)(sm + SM_QTT);
    ull*      ws    = (ull*)(sm + SM_WS);
    float*    a_s   = (float*)(sm + SM_A);
    float*    ta_s  = (float*)(sm + SM_TA);
    float*    red_s = (float*)(sm + SM_RED);

    const int pair = blockIdx.x;
    const int t = threadIdx.x;
    const float* qb = q + (size_t)pair * QL * DD;
    const float* kb = k + (size_t)pair * 256 * DD;
    const float* vb = v + (size_t)pair * 256 * DD;

    // ---- stage qT2 (all 256 threads) + ws ----
    {
        const float4* qs = (const float4*)qb;   // 1024 float4
        #pragma unroll
        for (int it = 0; it < 4; it++) {
            int idx = it * 256 + t;
            float4 f = qs[idx];
            int i = idx >> 6;
            int d0 = (idx & 63) * 4;
            qT2f[(d0 >> 1) * 16 + i]       = make_float2(f.x, f.y);
            qT2f[((d0 >> 1) + 1) * 16 + i] = make_float2(f.z, f.w);
        }
        if (t < 128) {
            float2 wv = *(const float2*)&g_w[2 * t];
            ws[t] = pack2(wv.x, wv.y);
        }
    }
    __syncthreads();

    if (t >= 128) {
        // ================= PRODUCERS (warps 4-7) =================
        const int pt = t - 128;
        #pragma unroll
        for (int s = 0; s < 4; s++) {
            unsigned* buf = kbuf[s & 1];
            const float4* ks = (const float4*)(kb + (size_t)(64 * s) * 256);
            #pragma unroll 4
            for (int it = 0; it < 32; it++) {
                int idx = it * 128 + pt;    // 4096 float4 per subtile
                float4 f = ks[idx];
                int row = idx >> 6;
                int e2a = (idx & 63) * 2;
                int off = row * KSTR + e2a + (e2a >> 5);
                buf[off]     = f2bf(f.x, f.y);
                buf[off + 1] = f2bf(f.z, f.w);
            }
            BARX(1);   // subtile s ready (meets consumers)
        }
        BARX(1);       // final stage boundary (consumers computing s=3)
    } else {
        // ================= CONSUMERS (warps 0-3) =================
        // Phase 1: Qt[i][e] = sum_d q[i][d]*A[d][e]; p = t (e-pair), 2 passes of 8 i
        {
            const int p = t;
            const uint2* A2 = (const uint2*)g_Au;
            const int base = p * 18 + (p >> 5) * 2;
            #pragma unroll
            for (int ih = 0; ih < 2; ih++) {
                ull acc0[8], acc1[8];
                #pragma unroll
                for (int i = 0; i < 8; i++) { acc0[i] = 0ull; acc1[i] = 0ull; }
                #pragma unroll 8
                for (int d2 = 0; d2 < 128; d2++) {
                    uint2 a = A2[d2 * 128 + p];
                    ull Ae0 = bf2w(a.x);
                    ull Ae1 = bf2w(a.y);
                    const ulonglong2* qp = (const ulonglong2*)(qT2f + d2 * 16 + ih * 8);
                    ulonglong2 qA = qp[0], qB = qp[1], qC = qp[2], qD = qp[3];
                    FFMA2(acc0[0], qA.x, Ae0); FFMA2(acc1[0], qA.x, Ae1);
                    FFMA2(acc0[1], qA.y, Ae0); FFMA2(acc1[1], qA.y, Ae1);
                    FFMA2(acc0[2], qB.x, Ae0); FFMA2(acc1[2], qB.x, Ae1);
                    FFMA2(acc0[3], qB.y, Ae0); FFMA2(acc1[3], qB.y, Ae1);
                    FFMA2(acc0[4], qC.x, Ae0); FFMA2(acc1[4], qC.x, Ae1);
                    FFMA2(acc0[5], qC.y, Ae0); FFMA2(acc1[5], qC.y, Ae1);
                    FFMA2(acc0[6], qD.x, Ae0); FFMA2(acc1[6], qD.x, Ae1);
                    FFMA2(acc0[7], qD.y, Ae0); FFMA2(acc1[7], qD.y, Ae1);
                }
                #pragma unroll
                for (int i = 0; i < 8; i++) {
                    float2 e0f = unpack2(acc0[i]);
                    float2 e1f = unpack2(acc1[i]);
                    Qtf[base + 8 * ih + i] = make_float2(e0f.x + e0f.y, e1f.x + e1f.y);
                }
            }
        }
        // a_i = q_i . u + c (warp 0)
        if (t < 32) {
            const float cc = g_c;
            for (int i = 0; i < QL; i++) {
                float p = 0.f;
                #pragma unroll
                for (int m = 0; m < 8; m++) {
                    int dd = t + 32 * m;
                    p += __ldg(&qb[i * 256 + dd]) * g_u[dd];
                }
                #pragma unroll
                for (int o = 16; o > 0; o >>= 1) p += __shfl_xor_sync(0xffffffffu, p, o);
                if (t == 0) a_s[i] = p + cc;
            }
        }
        BARX(1);   // wait subtile 0 + publish Qt/a

        // Phase 2: pipelined score compute. thread = (iq=t&3: 4 i's, g=t>>2: 2 rows)
        const int iq = t & 3;
        const int g  = t >> 2;
        #pragma unroll
        for (int s = 0; s < 4; s++) {
            const unsigned* kbase = kbuf[s & 1] + (2 * g) * KSTR;
            const float2*   Qbase = Qtf + 4 * iq;
            ull acc[8];          // [rr*4 + ii]
            #pragma unroll
            for (int i = 0; i < 8; i++) acc[i] = 0ull;
            ull wk0 = 0ull, wk1 = 0ull;
            #pragma unroll 4
            for (int j = 0; j < 128; j++) {
                int jj = j + (j >> 5);
                ull k0 = bf2w(kbase[jj]);
                ull k1 = bf2w(kbase[jj + KSTR]);
                ull w2 = ws[j];
                const ulonglong2* Qp = (const ulonglong2*)(Qbase + 18 * j + 2 * (j >> 5));
                ulonglong2 qA = Qp[0], qB = Qp[1];
                FFMA2(wk0, w2, k0);
                FFMA2(wk1, w2, k1);
                FFMA2(acc[0], qA.x, k0);
                FFMA2(acc[1], qA.y, k0);
                FFMA2(acc[2], qB.x, k0);
                FFMA2(acc[3], qB.y, k0);
                FFMA2(acc[4], qA.x, k1);
                FFMA2(acc[5], qA.y, k1);
                FFMA2(acc[6], qB.x, k1);
                FFMA2(acc[7], qB.y, k1);
            }
            // collapse, row max over 16 i (combine iq lanes: bits 0,1)
            float av[4];
            #pragma unroll
            for (int ii = 0; ii < 4; ii++) av[ii] = a_s[4 * iq + ii];
            #pragma unroll
            for (int rr = 0; rr < 2; rr++) {
                float m = -1e30f;
                #pragma unroll
                for (int ii = 0; ii < 4; ii++) {
                    float2 f = unpack2(acc[rr * 4 + ii]);
                    m = fmaxf(m, f.x + f.y + av[ii]);
                }
                m = fmaxf(m, __shfl_xor_sync(0xffffffffu, m, 1));
                m = fmaxf(m, __shfl_xor_sync(0xffffffffu, m, 2));
                float2 wf = unpack2(rr ? wk1 : wk0);
                if (iq == 0)
                    ta_s[64 * s + 2 * g + rr] = wf.x + wf.y + m;
            }
            BARX(1);   // done reading buf (s&1); producer may refill
        }
    }

    // ---- Phase 3: normalize, mask, softmax (all 256) ----
    float cnt;
    {
        float tv = ta_s[t];
        float ss = bsum(tv * tv, red_s, t);
        float inv = rsqrtf(ss);
        const int mm = g_mask_mode;
        bool masked;
        size_t mi = (size_t)pair * 256 + t;
        if (mm == 0)      masked = ((const unsigned char*)maskp)[mi] != 0;
        else if (mm == 1) masked = ((const int*)maskp)[mi] != 0;
        else              masked = ((const float*)maskp)[mi] != 0.f;
        float x = masked ? -10.f : tv * inv;
        cnt = bsum(masked ? 0.f : 1.f, red_s, t);
        float mx = bmax(x, red_s, t);
        float ex = __expf(x - mx);
        float se = bsum(ex, red_s, t);
        float attn = (cnt == 0.f) ? 0.f : ex / se;
        ta_s[t] = attn;
        __syncthreads();
    }

    // ---- Phase 4: tvec[j=t] = sum_v attn[v] * v[v][t] ----
    {
        float acc = 0.f;
        #pragma unroll 16
        for (int vv = 0; vv < 256; vv++)
            acc += ta_s[vv] * vb[vv * 256 + t];
        g_tvec[pair * 256 + t] = acc;
        if (t == 0) g_sA[pair] = (cnt > 0.f) ? 1.f : 0.f;
    }
}

// ---------------- output projection: OUT = TVEC @ WvT + sA*vb ----------------
__global__ void out_kernel(const float* __restrict__ vw_b, float* __restrict__ out)
{
    __shared__ float tvT[256 * 20];
    __shared__ float sA_s[16];
    __shared__ float vb_s[256];
    const int t = threadIdx.x;
    const int p0 = blockIdx.x * 16;
    vb_s[t] = vw_b[t];
    if (t < 16) sA_s[t] = g_sA[p0 + t];
    #pragma unroll
    for (int it = 0; it < 16; it++) {
        int idx = it * 256 + t;
        int r = idx >> 8, j = idx & 255;
        tvT[j * 20 + r] = g_tvec[(p0 + r) * 256 + j];
    }
    __syncthreads();
    float acc[16];
    #pragma unroll
    for (int r = 0; r < 16; r++) acc[r] = 0.f;
    #pragma unroll 4
    for (int j = 0; j < 256; j++) {
        float wv = g_WvT[j * 256 + t];
        const float4* T = (const float4*)&tvT[j * 20];
        float4 t0 = T[0], t1 = T[1], t2 = T[2], t3 = T[3];
        acc[0]  += t0.x * wv;  acc[1]  += t0.y * wv;
        acc[2]  += t0.z * wv;  acc[3]  += t0.w * wv;
        acc[4]  += t1.x * wv;  acc[5]  += t1.y * wv;
        acc[6]  += t1.z * wv;  acc[7]  += t1.w * wv;
        acc[8]  += t2.x * wv;  acc[9]  += t2.y * wv;
        acc[10] += t2.z * wv;  acc[11] += t2.w * wv;
        acc[12] += t3.x * wv;  acc[13] += t3.y * wv;
        acc[14] += t3.z * wv;  acc[15] += t3.w * wv;
    }
    #pragma unroll
    for (int r = 0; r < 16; r++)
        out[(size_t)(p0 + r) * 256 + t] = acc[r] + sA_s[r] * vb_s[t];
}

extern "C" void kernel_launch(void* const* d_in, const int* in_sizes, int n_in,
                              void* d_out, int out_size)
{
    const float* q    = (const float*)d_in[0];
    const float* k    = (const float*)d_in[1];
    const float* v    = (const float*)d_in[2];
    const void*  m    = d_in[3];
    const float* qw_w = (const float*)d_in[4];
    const float* qw_b = (const float*)d_in[5];
    const float* kw_w = (const float*)d_in[6];
    const float* kw_b = (const float*)d_in[7];
    const float* vw_w = (const float*)d_in[8];
    const float* vw_b = (const float*)d_in[9];
    float* out = (float*)d_out;
    (void)in_sizes; (void)n_in; (void)out_size;

    cudaFuncSetAttribute(fused_kernel, cudaFuncAttributeMaxDynamicSharedMemorySize, SM_TOT);

    setup_kernel<<<131, 256>>>(qw_w, qw_b, kw_w, kw_b, vw_w, m);
    fused_kernel<<<PAIRS, 256, SM_TOT>>>(q, k, v, m);
    out_kernel<<<64, 256>>>(vw_b, out);
}

// round 9
// speedup vs baseline: 1.9156x; 1.2914x over previous
#include <cuda_runtime.h>
#include <cuda_bf16.h>
#include <cstdint>

typedef unsigned long long ull;

#define PAIRS 1024
#define DD 256
#define QL 16

// ---------------- persistent scratch / precomputed ----------------
__device__ __nv_bfloat16 g_Aebf[256 * 256];  // M^T: [e][d] = M[d][e], bf16 (MMA B operand)
__device__ float    g_WvT[256 * 256];        // WvT[j][d] = vw_w[d][j]
__device__ float    g_u[256];
__device__ float    g_w[256];
__device__ float    g_c;
__device__ int      g_mask_mode;             // 0=u8 bool, 1=int32, 2=float32
__device__ unsigned g_Qtu[16384 * 128];      // Q-tilde bf16x2 words: [row=pair*16+i][e-word]
__device__ float    g_tvec[PAIRS * 256];     // attn . v  per pair
__device__ float    g_sA[PAIRS];             // 1 if any unmasked else 0

__device__ __forceinline__ unsigned f2bf(float a, float b) {
    __nv_bfloat162 h = __floats2bfloat162_rn(a, b);
    return *reinterpret_cast<unsigned*>(&h);
}
__device__ __forceinline__ uint32_t smem_to_u32(const void* p) {
    uint32_t a;
    asm("{ .reg .u64 tmp; cvta.to.shared.u64 tmp, %1; cvt.u32.u64 %0, tmp; }" : "=r"(a) : "l"(p));
    return a;
}
__device__ __forceinline__ void ldsm4(unsigned* r, uint32_t addr) {
    asm volatile("ldmatrix.sync.aligned.m8n8.x4.shared.b16 {%0,%1,%2,%3}, [%4];"
        : "=r"(r[0]), "=r"(r[1]), "=r"(r[2]), "=r"(r[3]) : "r"(addr));
}
__device__ __forceinline__ void mma16816(float* c, const unsigned* a, unsigned b0, unsigned b1) {
    asm volatile(
        "mma.sync.aligned.m16n8k16.row.col.f32.bf16.bf16.f32 "
        "{%0,%1,%2,%3}, {%4,%5,%6,%7}, {%8,%9}, {%0,%1,%2,%3};"
        : "+f"(c[0]), "+f"(c[1]), "+f"(c[2]), "+f"(c[3])
        : "r"(a[0]), "r"(a[1]), "r"(a[2]), "r"(a[3]), "r"(b0), "r"(b1));
}
#define BARX(id) asm volatile("bar.sync %0, 256;" :: "r"(id) : "memory")

// ---------------- setup kernel ----------------
__global__ void setup_kernel(const float* __restrict__ qw_w, const float* __restrict__ qw_b,
                             const float* __restrict__ kw_w, const float* __restrict__ kw_b,
                             const float* __restrict__ vw_w, const void* __restrict__ maskp)
{
    const int b = blockIdx.x;
    const int t = threadIdx.x;
    if (b < 64) {
        // M^T rows e0..e0+3 (col d = t):  M[d][e] = sum_c qw[c][d]*kw[c][e]
        const int e0 = b * 4;
        float a0 = 0.f, a1 = 0.f, a2 = 0.f, a3 = 0.f;
        for (int cb = 0; cb < 256; cb += 4) {
            float qv[4]; float4 kv[4];
            #pragma unroll
            for (int m = 0; m < 4; m++) qv[m] = qw_w[(cb + m) * 256 + t];
            #pragma unroll
            for (int m = 0; m < 4; m++) kv[m] = *(const float4*)&kw_w[(cb + m) * 256 + e0];
            #pragma unroll
            for (int m = 0; m < 4; m++) {
                a0 += qv[m] * kv[m].x; a1 += qv[m] * kv[m].y;
                a2 += qv[m] * kv[m].z; a3 += qv[m] * kv[m].w;
            }
        }
        g_Aebf[(e0 + 0) * 256 + t] = __float2bfloat16(a0);
        g_Aebf[(e0 + 1) * 256 + t] = __float2bfloat16(a1);
        g_Aebf[(e0 + 2) * 256 + t] = __float2bfloat16(a2);
        g_Aebf[(e0 + 3) * 256 + t] = __float2bfloat16(a3);
    } else if (b == 64) {
        float acc = 0.f;
        #pragma unroll 8
        for (int d = 0; d < 256; d++)
            acc += qw_w[d * 256 + t] * __ldg(&kw_b[d]);
        g_u[t] = acc;
    } else if (b == 65) {
        float acc = 0.f;
        #pragma unroll 8
        for (int d = 0; d < 256; d++)
            acc += kw_w[d * 256 + t] * __ldg(&qw_b[d]);
        g_w[t] = acc;
    } else if (b == 66) {
        if (t < 32) {
            float cp = 0.f;
            #pragma unroll
            for (int m = 0; m < 8; m++)
                cp += qw_b[t + 32 * m] * kw_b[t + 32 * m];
            #pragma unroll
            for (int o = 16; o > 0; o >>= 1) cp += __shfl_xor_sync(0xffffffffu, cp, o);
            if (t == 0) g_c = cp;
        }
        __shared__ int nf[2];
        if (t < 2) nf[t] = 0;
        __syncthreads();
        const unsigned* mw = (const unsigned*)maskp;
        int bad0 = 0, bad1 = 0;
        for (int i = t; i < 16384; i += 256) {
            unsigned w = mw[i];
            if (w > 1u) bad0 = 1;
            if (w != 0u && w != 0x3F800000u) bad1 = 1;
        }
        if (bad0) nf[0] = 1;
        if (bad1) nf[1] = 1;
        __syncthreads();
        if (t == 0) g_mask_mode = nf[0] ? (nf[1] ? 0 : 2) : 1;
    } else {
        __shared__ float s[32][33];
        const int bb = b - 67;
        const int di = (bb >> 3) * 32, jj = (bb & 7) * 32;
        const int tx = t & 31, ty = t >> 5;
        #pragma unroll
        for (int u2 = 0; u2 < 4; u2++)
            s[ty + 8 * u2][tx] = vw_w[(di + ty + 8 * u2) * 256 + (jj + tx)];
        __syncthreads();
        #pragma unroll
        for (int u2 = 0; u2 < 4; u2++)
            g_WvT[(jj + ty + 8 * u2) * 256 + (di + tx)] = s[tx][ty + 8 * u2];
    }
}

// ---------------- qt_gemm: Q~ = q @ M via mma.sync bf16 ----------------
// CTA tile 128 rows x 64 e-cols, K=256. grid = 128 m x 4 n = 512 CTAs.
// smem: A (q bf16) 128 rows x 512B, chunk^(r&7) swizzle: [0, 65536)
//       B (M^T bf16) 64 rows x 132 words: [65536, 99328)
#define QG_B 65536
#define QG_TOT 99328

__global__ void __launch_bounds__(256)
qt_gemm(const float* __restrict__ q)
{
    extern __shared__ unsigned char smem[];
    unsigned char* Ab = smem;
    unsigned* Bw = (unsigned*)(smem + QG_B);
    const int t = threadIdx.x;
    const int wid = t >> 5;
    const int lane = t & 31;
    const int lq = lane & 3, lr = lane >> 2;
    const int warpm = wid & 3, warpn = wid >> 2;
    const int tile_m = blockIdx.x >> 2;
    const int tile_n = blockIdx.x & 3;

    // Stage A: q rows [tile_m*128, +128) -> bf16, 512B rows, 16B-chunk c^(r&7)
    {
        const float4* qs = (const float4*)(q + (size_t)tile_m * 128 * 256);
        #pragma unroll 4
        for (int it = 0; it < 16; it++) {
            int idx = it * 256 + t;          // 4096 16B-chunks
            int row = idx >> 5, c = idx & 31;
            float4 fa = qs[idx * 2], fb = qs[idx * 2 + 1];
            uint4 val = make_uint4(f2bf(fa.x, fa.y), f2bf(fa.z, fa.w),
                                   f2bf(fb.x, fb.y), f2bf(fb.z, fb.w));
            *(uint4*)(Ab + row * 512 + ((c ^ (row & 7)) << 4)) = val;
        }
    }
    // Stage B: M^T rows [tile_n*64, +64), rows padded to 132 words
    {
        const uint4* asrc = (const uint4*)g_Aebf;   // 32 uint4 per e-row
        #pragma unroll 2
        for (int it = 0; it < 8; it++) {
            int idx = it * 256 + t;          // 2048
            int er = idx >> 5, c = idx & 31;
            uint4 v = asrc[(size_t)(tile_n * 64 + er) * 32 + c];
            *(uint4*)&Bw[er * 132 + c * 4] = v;
        }
    }
    __syncthreads();

    const uint32_t Abase = smem_to_u32(Ab);
    float acc[2][4][4];
    #pragma unroll
    for (int mt = 0; mt < 2; mt++)
        #pragma unroll
        for (int nt = 0; nt < 4; nt++)
            #pragma unroll
            for (int i = 0; i < 4; i++) acc[mt][nt][i] = 0.f;

    #pragma unroll 4
    for (int ks = 0; ks < 16; ks++) {
        unsigned a0[4], a1[4];
        #pragma unroll
        for (int mt = 0; mt < 2; mt++) {
            int r = warpm * 32 + mt * 16 + (lane & 15);
            int c = ks * 2 + (lane >> 4);
            uint32_t addr = Abase + r * 512 + ((c ^ (r & 7)) << 4);
            ldsm4(mt ? a1 : a0, addr);
        }
        unsigned b0[4], b1[4];
        #pragma unroll
        for (int nt = 0; nt < 4; nt++) {
            int bi = (warpn * 32 + nt * 8 + lr) * 132 + ks * 8 + lq;
            b0[nt] = Bw[bi];
            b1[nt] = Bw[bi + 4];
        }
        #pragma unroll
        for (int nt = 0; nt < 4; nt++) {
            mma16816(acc[0][nt], a0, b0[nt], b1[nt]);
            mma16816(acc[1][nt], a1, b0[nt], b1[nt]);
        }
    }

    // Epilogue: C -> bf16x2 words in g_Qtu
    #pragma unroll
    for (int mt = 0; mt < 2; mt++) {
        int row = tile_m * 128 + warpm * 32 + mt * 16 + lr;
        #pragma unroll
        for (int nt = 0; nt < 4; nt++) {
            int cw = tile_n * 32 + warpn * 16 + nt * 4 + lq;
            g_Qtu[(size_t)row * 128 + cw]       = f2bf(acc[mt][nt][0], acc[mt][nt][1]);
            g_Qtu[(size_t)(row + 8) * 128 + cw] = f2bf(acc[mt][nt][2], acc[mt][nt][3]);
        }
    }
}

// ---------------- fused per-pair kernel (mma.sync scores) ----------------
// smem (bytes):
//   [0,     32768)  kbuf0 : 64 rows x 512B bf16, chunk^(r&7)
//   [32768, 65536)  kbuf1
//   [65536, 78208)  Qtw   : 24 rows x 132 words (bf16x2); rows 0-15 = Qt, 16 = w, 17-23 = 0
//   [78208, 78272)  a_s   : 16 floats
//   [78272, 79296)  ta_s  : 256 floats
//   [79296, 79328)  red   : 8 floats
#define SM_QTW 65536
#define SM_A   78208
#define SM_TA  78272
#define SM_RED 79296
#define SM_TOT 79328

__device__ __forceinline__ float bsum(float v, float* red, int t) {
    __syncthreads();
    #pragma unroll
    for (int o = 16; o > 0; o >>= 1) v += __shfl_xor_sync(0xffffffffu, v, o);
    if ((t & 31) == 0) red[t >> 5] = v;
    __syncthreads();
    float r = red[0];
    #pragma unroll
    for (int i = 1; i < 8; i++) r += red[i];
    return r;
}
__device__ __forceinline__ float bmax(float v, float* red, int t) {
    __syncthreads();
    #pragma unroll
    for (int o = 16; o > 0; o >>= 1) v = fmaxf(v, __shfl_xor_sync(0xffffffffu, v, o));
    if ((t & 31) == 0) red[t >> 5] = v;
    __syncthreads();
    float r = red[0];
    #pragma unroll
    for (int i = 1; i < 8; i++) r = fmaxf(r, red[i]);
    return r;
}

__global__ void __launch_bounds__(256, 2)
fused_kernel(const float* __restrict__ q, const float* __restrict__ k,
             const float* __restrict__ v, const void* __restrict__ maskp)
{
    extern __shared__ unsigned char sm[];
    unsigned char* kb0 = sm;
    unsigned* Qtw   = (unsigned*)(sm + SM_QTW);
    float*    a_s   = (float*)(sm + SM_A);
    float*    ta_s  = (float*)(sm + SM_TA);
    float*    red_s = (float*)(sm + SM_RED);

    const int pair = blockIdx.x;
    const int t = threadIdx.x;
    const int lane = t & 31;
    const int lq = lane & 3, lr = lane >> 2;
    const float* qb = q + (size_t)pair * QL * DD;
    const float* kb = k + (size_t)pair * 256 * DD;
    const float* vb = v + (size_t)pair * 256 * DD;

    // ---- stage Qt rows 0-15, w row 16, zero rows 17-23 ----
    {
        const uint4* qtsrc = (const uint4*)(g_Qtu + (size_t)pair * 16 * 128);
        #pragma unroll
        for (int it = 0; it < 2; it++) {
            int idx = it * 256 + t;          // 512 uint4
            int row = idx >> 5, c = idx & 31;
            *(uint4*)&Qtw[row * 132 + c * 4] = qtsrc[idx];
        }
        if (t < 128) {
            float2 wv = *(const float2*)&g_w[2 * t];
            Qtw[16 * 132 + t] = f2bf(wv.x, wv.y);
        }
        for (int i = t; i < 924; i += 256) Qtw[17 * 132 + i] = 0u;
    }
    __syncthreads();

    if (t >= 128) {
        // ================= PRODUCERS (warps 4-7) =================
        const int pt = t - 128;
        #pragma unroll
        for (int s = 0; s < 4; s++) {
            unsigned char* buf = kb0 + (s & 1) * 32768;
            const float4* ks = (const float4*)(kb + (size_t)(64 * s) * 256);
            #pragma unroll 4
            for (int it = 0; it < 16; it++) {
                int idx = it * 128 + pt;     // 2048 16B-chunks
                int row = idx >> 5, c = idx & 31;
                float4 fa = ks[idx * 2], fb = ks[idx * 2 + 1];
                uint4 val = make_uint4(f2bf(fa.x, fa.y), f2bf(fa.z, fa.w),
                                       f2bf(fb.x, fb.y), f2bf(fb.z, fb.w));
                *(uint4*)(buf + row * 512 + ((c ^ (row & 7)) << 4)) = val;
            }
            BARX(1);
        }
        BARX(1);
    } else {
        // ================= CONSUMERS (warps 0-3) =================
        const int warpm = t >> 5;
        // a_i = q_i . u + c (warp 0)
        if (t < 32) {
            const float cc = g_c;
            for (int i = 0; i < QL; i++) {
                float p = 0.f;
                #pragma unroll
                for (int m = 0; m < 8; m++) {
                    int dd = t + 32 * m;
                    p += __ldg(&qb[i * 256 + dd]) * g_u[dd];
                }
                #pragma unroll
                for (int o = 16; o > 0; o >>= 1) p += __shfl_xor_sync(0xffffffffu, p, o);
                if (t == 0) a_s[i] = p + cc;
            }
        }
        BARX(1);   // subtile 0 ready; a_s/Qtw published

        const float a_e  = a_s[2 * lq];
        const float a_o  = a_s[2 * lq + 1];
        const float a_e8 = a_s[2 * lq + 8];
        const float a_o8 = a_s[2 * lq + 9];

        #pragma unroll
        for (int s = 0; s < 4; s++) {
            const uint32_t kbase = smem_to_u32(kb0 + (s & 1) * 32768);
            float c0[4], c1[4], cw[4];
            #pragma unroll
            for (int i = 0; i < 4; i++) { c0[i] = 0.f; c1[i] = 0.f; cw[i] = 0.f; }
            const int krow = warpm * 16 + (lane & 15);
            #pragma unroll 4
            for (int ks = 0; ks < 16; ks++) {
                unsigned a[4];
                int c = ks * 2 + (lane >> 4);
                ldsm4(a, kbase + krow * 512 + ((c ^ (krow & 7)) << 4));
                int w0 = lr * 132 + ks * 8 + lq;
                unsigned b00 = Qtw[w0],             b01 = Qtw[w0 + 4];
                unsigned b10 = Qtw[w0 + 8 * 132],   b11 = Qtw[w0 + 8 * 132 + 4];
                unsigned b20 = Qtw[w0 + 16 * 132],  b21 = Qtw[w0 + 16 * 132 + 4];
                mma16816(c0, a, b00, b01);
                mma16816(c1, a, b10, b11);
                mma16816(cw, a, b20, b21);
            }
            // epilogue: row r = lr, r+8 of this warp's 16-row m-tile
            float mr  = fmaxf(fmaxf(c0[0] + a_e, c0[1] + a_o), fmaxf(c1[0] + a_e8, c1[1] + a_o8));
            float mr8 = fmaxf(fmaxf(c0[2] + a_e, c0[3] + a_o), fmaxf(c1[2] + a_e8, c1[3] + a_o8));
            mr  = fmaxf(mr,  __shfl_xor_sync(0xffffffffu, mr, 1));
            mr  = fmaxf(mr,  __shfl_xor_sync(0xffffffffu, mr, 2));
            mr8 = fmaxf(mr8, __shfl_xor_sync(0xffffffffu, mr8, 1));
            mr8 = fmaxf(mr8, __shfl_xor_sync(0xffffffffu, mr8, 2));
            float wkr  = __shfl_sync(0xffffffffu, cw[0], lane & ~3);
            float wkr8 = __shfl_sync(0xffffffffu, cw[2], lane & ~3);
            if (lq == 0) {
                ta_s[s * 64 + warpm * 16 + lr]     = wkr + mr;
                ta_s[s * 64 + warpm * 16 + lr + 8] = wkr8 + mr8;
            }
            BARX(1);
        }
    }

    // ---- Phase 3: normalize, mask, softmax (all 256) ----
    float cnt;
    {
        float tv = ta_s[t];
        float ss = bsum(tv * tv, red_s, t);
        float inv = rsqrtf(ss);
        const int mm = g_mask_mode;
        bool masked;
        size_t mi = (size_t)pair * 256 + t;
        if (mm == 0)      masked = ((const unsigned char*)maskp)[mi] != 0;
        else if (mm == 1) masked = ((const int*)maskp)[mi] != 0;
        else              masked = ((const float*)maskp)[mi] != 0.f;
        float x = masked ? -10.f : tv * inv;
        cnt = bsum(masked ? 0.f : 1.f, red_s, t);
        float mx = bmax(x, red_s, t);
        float ex = __expf(x - mx);
        float se = bsum(ex, red_s, t);
        float attn = (cnt == 0.f) ? 0.f : ex / se;
        ta_s[t] = attn;
        __syncthreads();
    }

    // ---- Phase 4: tvec[j=t] = sum_v attn[v] * v[v][t] ----
    {
        float acc = 0.f;
        #pragma unroll 16
        for (int vv = 0; vv < 256; vv++)
            acc += ta_s[vv] * vb[vv * 256 + t];
        g_tvec[pair * 256 + t] = acc;
        if (t == 0) g_sA[pair] = (cnt > 0.f) ? 1.f : 0.f;
    }
}

// ---------------- output projection: OUT = TVEC @ WvT + sA*vb ----------------
__global__ void out_kernel(const float* __restrict__ vw_b, float* __restrict__ out)
{
    __shared__ float tvT[256 * 20];
    __shared__ float sA_s[16];
    __shared__ float vb_s[256];
    const int t = threadIdx.x;
    const int p0 = blockIdx.x * 16;
    vb_s[t] = vw_b[t];
    if (t < 16) sA_s[t] = g_sA[p0 + t];
    #pragma unroll
    for (int it = 0; it < 16; it++) {
        int idx = it * 256 + t;
        int r = idx >> 8, j = idx & 255;
        tvT[j * 20 + r] = g_tvec[(p0 + r) * 256 + j];
    }
    __syncthreads();
    float acc[16];
    #pragma unroll
    for (int r = 0; r < 16; r++) acc[r] = 0.f;
    #pragma unroll 4
    for (int j = 0; j < 256; j++) {
        float wv = g_WvT[j * 256 + t];
        const float4* T = (const float4*)&tvT[j * 20];
        float4 t0 = T[0], t1 = T[1], t2 = T[2], t3 = T[3];
        acc[0]  += t0.x * wv;  acc[1]  += t0.y * wv;
        acc[2]  += t0.z * wv;  acc[3]  += t0.w * wv;
        acc[4]  += t1.x * wv;  acc[5]  += t1.y * wv;
        acc[6]  += t1.z * wv;  acc[7]  += t1.w * wv;
        acc[8]  += t2.x * wv;  acc[9]  += t2.y * wv;
        acc[10] += t2.z * wv;  acc[11] += t2.w * wv;
        acc[12] += t3.x * wv;  acc[13] += t3.y * wv;
        acc[14] += t3.z * wv;  acc[15] += t3.w * wv;
    }
    #pragma unroll
    for (int r = 0; r < 16; r++)
        out[(size_t)(p0 + r) * 256 + t] = acc[r] + sA_s[r] * vb_s[t];
}

extern "C" void kernel_launch(void* const* d_in, const int* in_sizes, int n_in,
                              void* d_out, int out_size)
{
    const float* q    = (const float*)d_in[0];
    const float* k    = (const float*)d_in[1];
    const float* v    = (const float*)d_in[2];
    const void*  m    = d_in[3];
    const float* qw_w = (const float*)d_in[4];
    const float* qw_b = (const float*)d_in[5];
    const float* kw_w = (const float*)d_in[6];
    const float* kw_b = (const float*)d_in[7];
    const float* vw_w = (const float*)d_in[8];
    const float* vw_b = (const float*)d_in[9];
    float* out = (float*)d_out;
    (void)in_sizes; (void)n_in; (void)out_size;

    cudaFuncSetAttribute(qt_gemm, cudaFuncAttributeMaxDynamicSharedMemorySize, QG_TOT);
    cudaFuncSetAttribute(fused_kernel, cudaFuncAttributeMaxDynamicSharedMemorySize, SM_TOT);

    setup_kernel<<<131, 256>>>(qw_w, qw_b, kw_w, kw_b, vw_w, m);
    qt_gemm<<<512, 256, QG_TOT>>>(q);
    fused_kernel<<<PAIRS, 256, SM_TOT>>>(q, k, v, m);
    out_kernel<<<64, 256>>>(vw_b, out);
}

// round 10
// speedup vs baseline: 1.9910x; 1.0394x over previous
#include <cuda_runtime.h>
#include <cuda_bf16.h>
#include <cstdint>

typedef unsigned long long ull;

#define PAIRS 1024
#define DD 256
#define QL 16

// ---------------- persistent scratch / precomputed ----------------
__device__ __nv_bfloat16 g_Aebf[256 * 256];  // M^T: [e][d] = M[d][e], bf16 (MMA B operand)
__device__ float    g_WvT[256 * 256];        // WvT[j][d] = vw_w[d][j]
__device__ float    g_u[256];
__device__ float    g_w[256];
__device__ float    g_c;
__device__ int      g_mask_mode;             // 0=u8 bool, 1=int32, 2=float32
__device__ unsigned g_Qtu[16384 * 128];      // Q-tilde bf16x2 words: [row=pair*16+i][e-word]
__device__ float    g_tvec[PAIRS * 256];     // attn . v  per pair
__device__ float    g_sA[PAIRS];             // 1 if any unmasked else 0

__device__ __forceinline__ unsigned f2bf(float a, float b) {
    __nv_bfloat162 h = __floats2bfloat162_rn(a, b);
    return *reinterpret_cast<unsigned*>(&h);
}
__device__ __forceinline__ uint32_t smem_to_u32(const void* p) {
    uint32_t a;
    asm("{ .reg .u64 tmp; cvta.to.shared.u64 tmp, %1; cvt.u32.u64 %0, tmp; }" : "=r"(a) : "l"(p));
    return a;
}
__device__ __forceinline__ void ldsm4(unsigned* r, uint32_t addr) {
    asm volatile("ldmatrix.sync.aligned.m8n8.x4.shared.b16 {%0,%1,%2,%3}, [%4];"
        : "=r"(r[0]), "=r"(r[1]), "=r"(r[2]), "=r"(r[3]) : "r"(addr));
}
__device__ __forceinline__ void mma16816(float* c, const unsigned* a, unsigned b0, unsigned b1) {
    asm volatile(
        "mma.sync.aligned.m16n8k16.row.col.f32.bf16.bf16.f32 "
        "{%0,%1,%2,%3}, {%4,%5,%6,%7}, {%8,%9}, {%0,%1,%2,%3};"
        : "+f"(c[0]), "+f"(c[1]), "+f"(c[2]), "+f"(c[3])
        : "r"(a[0]), "r"(a[1]), "r"(a[2]), "r"(a[3]), "r"(b0), "r"(b1));
}
#define BARX(id) asm volatile("bar.sync %0, 256;" :: "r"(id) : "memory")

// ---------------- setup kernel ----------------
__global__ void setup_kernel(const float* __restrict__ qw_w, const float* __restrict__ qw_b,
                             const float* __restrict__ kw_w, const float* __restrict__ kw_b,
                             const float* __restrict__ vw_w, const void* __restrict__ maskp)
{
    const int b = blockIdx.x;
    const int t = threadIdx.x;
    if (b < 128) {
        // M^T rows e0, e0+1 (col d = t):  M[d][e] = sum_c qw[c][d]*kw[c][e]
        const int e0 = b * 2;
        float a0 = 0.f, a1 = 0.f;
        for (int cb = 0; cb < 256; cb += 8) {
            float qv[8]; float2 kv[8];
            #pragma unroll
            for (int m = 0; m < 8; m++) qv[m] = qw_w[(cb + m) * 256 + t];
            #pragma unroll
            for (int m = 0; m < 8; m++) kv[m] = *(const float2*)&kw_w[(cb + m) * 256 + e0];
            #pragma unroll
            for (int m = 0; m < 8; m++) { a0 += qv[m] * kv[m].x; a1 += qv[m] * kv[m].y; }
        }
        g_Aebf[(e0 + 0) * 256 + t] = __float2bfloat16(a0);
        g_Aebf[(e0 + 1) * 256 + t] = __float2bfloat16(a1);
    } else if (b == 128) {
        float acc = 0.f;
        #pragma unroll 8
        for (int d = 0; d < 256; d++)
            acc += qw_w[d * 256 + t] * __ldg(&kw_b[d]);
        g_u[t] = acc;
    } else if (b == 129) {
        float acc = 0.f;
        #pragma unroll 8
        for (int d = 0; d < 256; d++)
            acc += kw_w[d * 256 + t] * __ldg(&qw_b[d]);
        g_w[t] = acc;
    } else if (b == 130) {
        if (t < 32) {
            float cp = 0.f;
            #pragma unroll
            for (int m = 0; m < 8; m++)
                cp += qw_b[t + 32 * m] * kw_b[t + 32 * m];
            #pragma unroll
            for (int o = 16; o > 0; o >>= 1) cp += __shfl_xor_sync(0xffffffffu, cp, o);
            if (t == 0) g_c = cp;
        }
        __shared__ int nf[2];
        if (t < 2) nf[t] = 0;
        __syncthreads();
        const unsigned* mw = (const unsigned*)maskp;
        int bad0 = 0, bad1 = 0;
        for (int i = t; i < 16384; i += 256) {
            unsigned w = mw[i];
            if (w > 1u) bad0 = 1;
            if (w != 0u && w != 0x3F800000u) bad1 = 1;
        }
        if (bad0) nf[0] = 1;
        if (bad1) nf[1] = 1;
        __syncthreads();
        if (t == 0) g_mask_mode = nf[0] ? (nf[1] ? 0 : 2) : 1;
    } else {
        __shared__ float s[32][33];
        const int bb = b - 131;
        const int di = (bb >> 3) * 32, jj = (bb & 7) * 32;
        const int tx = t & 31, ty = t >> 5;
        #pragma unroll
        for (int u2 = 0; u2 < 4; u2++)
            s[ty + 8 * u2][tx] = vw_w[(di + ty + 8 * u2) * 256 + (jj + tx)];
        __syncthreads();
        #pragma unroll
        for (int u2 = 0; u2 < 4; u2++)
            g_WvT[(jj + ty + 8 * u2) * 256 + (di + tx)] = s[tx][ty + 8 * u2];
    }
}

// ---------------- qt_gemm: Q~ = q @ M via mma.sync bf16 ----------------
// CTA tile 128 rows x 64 e-cols, K=256. grid = 128 m x 4 n = 512 CTAs.
// smem: A (q bf16) 128 rows x 512B, chunk^(r&7) swizzle: [0, 65536)
//       B (M^T bf16) 64 rows x 132 words: [65536, 99328)
#define QG_B 65536
#define QG_TOT 99328

__global__ void __launch_bounds__(256)
qt_gemm(const float* __restrict__ q)
{
    extern __shared__ unsigned char smem[];
    unsigned char* Ab = smem;
    unsigned* Bw = (unsigned*)(smem + QG_B);
    const int t = threadIdx.x;
    const int wid = t >> 5;
    const int lane = t & 31;
    const int lq = lane & 3, lr = lane >> 2;
    const int warpm = wid & 3, warpn = wid >> 2;
    const int tile_m = blockIdx.x >> 2;
    const int tile_n = blockIdx.x & 3;

    // Stage A: q rows [tile_m*128, +128) -> bf16, 512B rows, 16B-chunk c^(r&7)
    {
        const float4* qs = (const float4*)(q + (size_t)tile_m * 128 * 256);
        #pragma unroll 4
        for (int it = 0; it < 16; it++) {
            int idx = it * 256 + t;          // 4096 16B-chunks
            int row = idx >> 5, c = idx & 31;
            float4 fa = qs[idx * 2], fb = qs[idx * 2 + 1];
            uint4 val = make_uint4(f2bf(fa.x, fa.y), f2bf(fa.z, fa.w),
                                   f2bf(fb.x, fb.y), f2bf(fb.z, fb.w));
            *(uint4*)(Ab + row * 512 + ((c ^ (row & 7)) << 4)) = val;
        }
    }
    // Stage B: M^T rows [tile_n*64, +64), rows padded to 132 words
    {
        const uint4* asrc = (const uint4*)g_Aebf;   // 32 uint4 per e-row
        #pragma unroll 2
        for (int it = 0; it < 8; it++) {
            int idx = it * 256 + t;          // 2048
            int er = idx >> 5, c = idx & 31;
            uint4 v = asrc[(size_t)(tile_n * 64 + er) * 32 + c];
            *(uint4*)&Bw[er * 132 + c * 4] = v;
        }
    }
    __syncthreads();

    const uint32_t Abase = smem_to_u32(Ab);
    float acc[2][4][4];
    #pragma unroll
    for (int mt = 0; mt < 2; mt++)
        #pragma unroll
        for (int nt = 0; nt < 4; nt++)
            #pragma unroll
            for (int i = 0; i < 4; i++) acc[mt][nt][i] = 0.f;

    #pragma unroll 4
    for (int ks = 0; ks < 16; ks++) {
        unsigned a0[4], a1[4];
        #pragma unroll
        for (int mt = 0; mt < 2; mt++) {
            int r = warpm * 32 + mt * 16 + (lane & 15);
            int c = ks * 2 + (lane >> 4);
            uint32_t addr = Abase + r * 512 + ((c ^ (r & 7)) << 4);
            ldsm4(mt ? a1 : a0, addr);
        }
        unsigned b0[4], b1[4];
        #pragma unroll
        for (int nt = 0; nt < 4; nt++) {
            int bi = (warpn * 32 + nt * 8 + lr) * 132 + ks * 8 + lq;
            b0[nt] = Bw[bi];
            b1[nt] = Bw[bi + 4];
        }
        #pragma unroll
        for (int nt = 0; nt < 4; nt++) {
            mma16816(acc[0][nt], a0, b0[nt], b1[nt]);
            mma16816(acc[1][nt], a1, b0[nt], b1[nt]);
        }
    }

    // Epilogue: C -> bf16x2 words in g_Qtu
    #pragma unroll
    for (int mt = 0; mt < 2; mt++) {
        int row = tile_m * 128 + warpm * 32 + mt * 16 + lr;
        #pragma unroll
        for (int nt = 0; nt < 4; nt++) {
            int cw = tile_n * 32 + warpn * 16 + nt * 4 + lq;
            g_Qtu[(size_t)row * 128 + cw]       = f2bf(acc[mt][nt][0], acc[mt][nt][1]);
            g_Qtu[(size_t)(row + 8) * 128 + cw] = f2bf(acc[mt][nt][2], acc[mt][nt][3]);
        }
    }
}

// ---------------- fused per-pair kernel (mma.sync scores) ----------------
// smem (bytes):
//   [0,     32768)  kbuf0 : 64 rows x 512B bf16, chunk^(r&7)
//   [32768, 65536)  kbuf1
//   [65536, 78208)  Qtw   : 24 rows x 132 words (bf16x2); rows 0-15 = Qt, 16 = w, 17-23 = 0
//   [78208, 78272)  a_s   : 16 floats
//   [78272, 79296)  ta_s  : 256 floats
//   [79296, 79328)  red   : 8 floats
#define SM_QTW 65536
#define SM_A   78208
#define SM_TA  78272
#define SM_RED 79296
#define SM_TOT 79328

__device__ __forceinline__ float bsum(float v, float* red, int t) {
    __syncthreads();
    #pragma unroll
    for (int o = 16; o > 0; o >>= 1) v += __shfl_xor_sync(0xffffffffu, v, o);
    if ((t & 31) == 0) red[t >> 5] = v;
    __syncthreads();
    float r = red[0];
    #pragma unroll
    for (int i = 1; i < 8; i++) r += red[i];
    return r;
}
__device__ __forceinline__ float bmax(float v, float* red, int t) {
    __syncthreads();
    #pragma unroll
    for (int o = 16; o > 0; o >>= 1) v = fmaxf(v, __shfl_xor_sync(0xffffffffu, v, o));
    if ((t & 31) == 0) red[t >> 5] = v;
    __syncthreads();
    float r = red[0];
    #pragma unroll
    for (int i = 1; i < 8; i++) r = fmaxf(r, red[i]);
    return r;
}

__global__ void __launch_bounds__(256, 2)
fused_kernel(const float* __restrict__ q, const float* __restrict__ k,
             const float* __restrict__ v, const void* __restrict__ maskp)
{
    extern __shared__ unsigned char sm[];
    unsigned char* kb0 = sm;
    unsigned* Qtw   = (unsigned*)(sm + SM_QTW);
    float*    a_s   = (float*)(sm + SM_A);
    float*    ta_s  = (float*)(sm + SM_TA);
    float*    red_s = (float*)(sm + SM_RED);

    const int pair = blockIdx.x;
    const int t = threadIdx.x;
    const int lane = t & 31;
    const int lq = lane & 3, lr = lane >> 2;
    const float* qb = q + (size_t)pair * QL * DD;
    const float* kb = k + (size_t)pair * 256 * DD;
    const float* vb = v + (size_t)pair * 256 * DD;

    // ---- stage Qt rows 0-15, w row 16, zero rows 17-23 ----
    {
        const uint4* qtsrc = (const uint4*)(g_Qtu + (size_t)pair * 16 * 128);
        #pragma unroll
        for (int it = 0; it < 2; it++) {
            int idx = it * 256 + t;          // 512 uint4
            int row = idx >> 5, c = idx & 31;
            *(uint4*)&Qtw[row * 132 + c * 4] = qtsrc[idx];
        }
        if (t < 128) {
            float2 wv = *(const float2*)&g_w[2 * t];
            Qtw[16 * 132 + t] = f2bf(wv.x, wv.y);
        }
        for (int i = t; i < 924; i += 256) Qtw[17 * 132 + i] = 0u;
    }
    __syncthreads();

    if (t >= 128) {
        // ================= PRODUCERS (warps 4-7) =================
        const int pt = t - 128;
        #pragma unroll
        for (int s = 0; s < 4; s++) {
            unsigned char* buf = kb0 + (s & 1) * 32768;
            const float4* ks = (const float4*)(kb + (size_t)(64 * s) * 256);
            #pragma unroll 4
            for (int it = 0; it < 16; it++) {
                int idx = it * 128 + pt;     // 2048 16B-chunks
                int row = idx >> 5, c = idx & 31;
                float4 fa = ks[idx * 2], fb = ks[idx * 2 + 1];
                uint4 val = make_uint4(f2bf(fa.x, fa.y), f2bf(fa.z, fa.w),
                                       f2bf(fb.x, fb.y), f2bf(fb.z, fb.w));
                *(uint4*)(buf + row * 512 + ((c ^ (row & 7)) << 4)) = val;
            }
            BARX(1);
        }
        BARX(1);
    } else {
        // ================= CONSUMERS (warps 0-3) =================
        const int warpm = t >> 5;
        // a_i = q_i . u + c (warp 0)
        if (t < 32) {
            const float cc = g_c;
            for (int i = 0; i < QL; i++) {
                float p = 0.f;
                #pragma unroll
                for (int m = 0; m < 8; m++) {
                    int dd = t + 32 * m;
                    p += __ldg(&qb[i * 256 + dd]) * g_u[dd];
                }
                #pragma unroll
                for (int o = 16; o > 0; o >>= 1) p += __shfl_xor_sync(0xffffffffu, p, o);
                if (t == 0) a_s[i] = p + cc;
            }
        }
        BARX(1);   // subtile 0 ready; a_s/Qtw published

        const float a_e  = a_s[2 * lq];
        const float a_o  = a_s[2 * lq + 1];
        const float a_e8 = a_s[2 * lq + 8];
        const float a_o8 = a_s[2 * lq + 9];

        #pragma unroll
        for (int s = 0; s < 4; s++) {
            const uint32_t kbase = smem_to_u32(kb0 + (s & 1) * 32768);
            float c0[4], c1[4], cw[4];
            #pragma unroll
            for (int i = 0; i < 4; i++) { c0[i] = 0.f; c1[i] = 0.f; cw[i] = 0.f; }
            const int krow = warpm * 16 + (lane & 15);
            #pragma unroll 4
            for (int ks = 0; ks < 16; ks++) {
                unsigned a[4];
                int c = ks * 2 + (lane >> 4);
                ldsm4(a, kbase + krow * 512 + ((c ^ (krow & 7)) << 4));
                int w0 = lr * 132 + ks * 8 + lq;
                unsigned b00 = Qtw[w0],             b01 = Qtw[w0 + 4];
                unsigned b10 = Qtw[w0 + 8 * 132],   b11 = Qtw[w0 + 8 * 132 + 4];
                unsigned b20 = Qtw[w0 + 16 * 132],  b21 = Qtw[w0 + 16 * 132 + 4];
                mma16816(c0, a, b00, b01);
                mma16816(c1, a, b10, b11);
                mma16816(cw, a, b20, b21);
            }
            // epilogue: row r = lr, r+8 of this warp's 16-row m-tile
            float mr  = fmaxf(fmaxf(c0[0] + a_e, c0[1] + a_o), fmaxf(c1[0] + a_e8, c1[1] + a_o8));
            float mr8 = fmaxf(fmaxf(c0[2] + a_e, c0[3] + a_o), fmaxf(c1[2] + a_e8, c1[3] + a_o8));
            mr  = fmaxf(mr,  __shfl_xor_sync(0xffffffffu, mr, 1));
            mr  = fmaxf(mr,  __shfl_xor_sync(0xffffffffu, mr, 2));
            mr8 = fmaxf(mr8, __shfl_xor_sync(0xffffffffu, mr8, 1));
            mr8 = fmaxf(mr8, __shfl_xor_sync(0xffffffffu, mr8, 2));
            float wkr  = __shfl_sync(0xffffffffu, cw[0], lane & ~3);
            float wkr8 = __shfl_sync(0xffffffffu, cw[2], lane & ~3);
            if (lq == 0) {
                ta_s[s * 64 + warpm * 16 + lr]     = wkr + mr;
                ta_s[s * 64 + warpm * 16 + lr + 8] = wkr8 + mr8;
            }
            BARX(1);
        }
    }

    // ---- Phase 3: normalize, mask, softmax (all 256) ----
    float cnt;
    {
        float tv = ta_s[t];
        float ss = bsum(tv * tv, red_s, t);
        float inv = rsqrtf(ss);
        const int mm = g_mask_mode;
        bool masked;
        size_t mi = (size_t)pair * 256 + t;
        if (mm == 0)      masked = ((const unsigned char*)maskp)[mi] != 0;
        else if (mm == 1) masked = ((const int*)maskp)[mi] != 0;
        else              masked = ((const float*)maskp)[mi] != 0.f;
        float x = masked ? -10.f : tv * inv;
        cnt = bsum(masked ? 0.f : 1.f, red_s, t);
        float mx = bmax(x, red_s, t);
        float ex = __expf(x - mx);
        float se = bsum(ex, red_s, t);
        float attn = (cnt == 0.f) ? 0.f : ex / se;
        ta_s[t] = attn;
        __syncthreads();
    }

    // ---- Phase 4: tvec[j=t] = sum_v attn[v] * v[v][t] ----
    {
        float acc = 0.f;
        #pragma unroll 16
        for (int vv = 0; vv < 256; vv++)
            acc += ta_s[vv] * vb[vv * 256 + t];
        g_tvec[pair * 256 + t] = acc;
        if (t == 0) g_sA[pair] = (cnt > 0.f) ? 1.f : 0.f;
    }
}

// ---------------- output projection: OUT = TVEC @ WvT + sA*vb ----------------
// grid = 64 pair-groups x 4 col-chunks = 256 blocks; thread: 4 rows x 1 col.
__global__ void __launch_bounds__(256)
out_kernel(const float* __restrict__ vw_b, float* __restrict__ out)
{
    __shared__ float tv[256 * 17];     // [j*17 + r]
    __shared__ float sA_s[16];
    __shared__ float vb_s[64];
    const int t = threadIdx.x;
    const int p0 = (blockIdx.x >> 2) * 16;
    const int c0 = (blockIdx.x & 3) * 64;
    const int c  = c0 + (t & 63);
    const int rg = t >> 6;             // 0..3
    if (t < 64) vb_s[t] = vw_b[c0 + t];
    if (t < 16) sA_s[t] = g_sA[p0 + t];
    #pragma unroll
    for (int it = 0; it < 16; it++) {
        int idx = it * 256 + t;        // 4096 elems
        int r = idx >> 8, j = idx & 255;
        tv[j * 17 + r] = g_tvec[(p0 + r) * 256 + j];
    }
    __syncthreads();
    float acc0 = 0.f, acc1 = 0.f, acc2 = 0.f, acc3 = 0.f;
    const float* Wcol = g_WvT + c;
    #pragma unroll 8
    for (int j = 0; j < 256; j++) {
        float wv = __ldg(&Wcol[j * 256]);
        const float* T = &tv[j * 17];
        acc0 += T[rg]      * wv;
        acc1 += T[rg + 4]  * wv;
        acc2 += T[rg + 8]  * wv;
        acc3 += T[rg + 12] * wv;
    }
    const float vbc = vb_s[t & 63];
    out[(size_t)(p0 + rg)      * 256 + c] = acc0 + sA_s[rg]      * vbc;
    out[(size_t)(p0 + rg + 4)  * 256 + c] = acc1 + sA_s[rg + 4]  * vbc;
    out[(size_t)(p0 + rg + 8)  * 256 + c] = acc2 + sA_s[rg + 8]  * vbc;
    out[(size_t)(p0 + rg + 12) * 256 + c] = acc3 + sA_s[rg + 12] * vbc;
}

extern "C" void kernel_launch(void* const* d_in, const int* in_sizes, int n_in,
                              void* d_out, int out_size)
{
    const float* q    = (const float*)d_in[0];
    const float* k    = (const float*)d_in[1];
    const float* v    = (const float*)d_in[2];
    const void*  m    = d_in[3];
    const float* qw_w = (const float*)d_in[4];
    const float* qw_b = (const float*)d_in[5];
    const float* kw_w = (const float*)d_in[6];
    const float* kw_b = (const float*)d_in[7];
    const float* vw_w = (const float*)d_in[8];
    const float* vw_b = (const float*)d_in[9];
    float* out = (float*)d_out;
    (void)in_sizes; (void)n_in; (void)out_size;

    cudaFuncSetAttribute(qt_gemm, cudaFuncAttributeMaxDynamicSharedMemorySize, QG_TOT);
    cudaFuncSetAttribute(fused_kernel, cudaFuncAttributeMaxDynamicSharedMemorySize, SM_TOT);

    setup_kernel<<<195, 256>>>(qw_w, qw_b, kw_w, kw_b, vw_w, m);
    qt_gemm<<<512, 256, QG_TOT>>>(q);
    fused_kernel<<<PAIRS, 256, SM_TOT>>>(q, k, v, m);
    out_kernel<<<256, 256>>>(vw_b, out);
}

// round 11
// speedup vs baseline: 2.1305x; 1.0701x over previous
#include <cuda_runtime.h>
#include <cuda_bf16.h>
#include <cstdint>

typedef unsigned long long ull;

#define PAIRS 1024
#define DD 256
#define QL 16

// ---------------- persistent scratch / precomputed ----------------
__device__ __nv_bfloat16 g_Aebf[256 * 256];  // M^T: [e][d] = M[d][e], bf16 (MMA B operand)
__device__ float    g_WvT[256 * 256];        // WvT[j][d] = vw_w[d][j]
__device__ float    g_u[256];
__device__ float    g_w[256];
__device__ float    g_c;
__device__ int      g_mask_mode;             // 0=u8 bool, 1=int32, 2=float32
__device__ unsigned g_Qtu[16384 * 128];      // Q-tilde bf16x2 words: [row=pair*16+i][e-word]
__device__ float    g_tvec[PAIRS * 256];     // attn . v  per pair
__device__ float    g_sA[PAIRS];             // 1 if any unmasked else 0
__device__ float    g_opart[4 * PAIRS * 256];// split-K partials [kc][row][c]

__device__ __forceinline__ unsigned f2bf(float a, float b) {
    __nv_bfloat162 h = __floats2bfloat162_rn(a, b);
    return *reinterpret_cast<unsigned*>(&h);
}
__device__ __forceinline__ uint32_t smem_to_u32(const void* p) {
    uint32_t a;
    asm("{ .reg .u64 tmp; cvta.to.shared.u64 tmp, %1; cvt.u32.u64 %0, tmp; }" : "=r"(a) : "l"(p));
    return a;
}
__device__ __forceinline__ void ldsm4(unsigned* r, uint32_t addr) {
    asm volatile("ldmatrix.sync.aligned.m8n8.x4.shared.b16 {%0,%1,%2,%3}, [%4];"
        : "=r"(r[0]), "=r"(r[1]), "=r"(r[2]), "=r"(r[3]) : "r"(addr));
}
__device__ __forceinline__ void mma16816(float* c, const unsigned* a, unsigned b0, unsigned b1) {
    asm volatile(
        "mma.sync.aligned.m16n8k16.row.col.f32.bf16.bf16.f32 "
        "{%0,%1,%2,%3}, {%4,%5,%6,%7}, {%8,%9}, {%0,%1,%2,%3};"
        : "+f"(c[0]), "+f"(c[1]), "+f"(c[2]), "+f"(c[3])
        : "r"(a[0]), "r"(a[1]), "r"(a[2]), "r"(a[3]), "r"(b0), "r"(b1));
}
#define BARX(id) asm volatile("bar.sync %0, 256;" :: "r"(id) : "memory")
#define PREF_L2(p) asm volatile("prefetch.global.L2 [%0];" :: "l"(p))

// ---------------- setup kernel ----------------
__global__ void setup_kernel(const float* __restrict__ qw_w, const float* __restrict__ qw_b,
                             const float* __restrict__ kw_w, const float* __restrict__ kw_b,
                             const float* __restrict__ vw_w, const void* __restrict__ maskp)
{
    const int b = blockIdx.x;
    const int t = threadIdx.x;
    if (b < 128) {
        // M^T rows e0, e0+1 (col d = t):  M[d][e] = sum_c qw[c][d]*kw[c][e]
        const int e0 = b * 2;
        float a0 = 0.f, a1 = 0.f;
        for (int cb = 0; cb < 256; cb += 8) {
            float qv[8]; float2 kv[8];
            #pragma unroll
            for (int m = 0; m < 8; m++) qv[m] = qw_w[(cb + m) * 256 + t];
            #pragma unroll
            for (int m = 0; m < 8; m++) kv[m] = *(const float2*)&kw_w[(cb + m) * 256 + e0];
            #pragma unroll
            for (int m = 0; m < 8; m++) { a0 += qv[m] * kv[m].x; a1 += qv[m] * kv[m].y; }
        }
        g_Aebf[(e0 + 0) * 256 + t] = __float2bfloat16(a0);
        g_Aebf[(e0 + 1) * 256 + t] = __float2bfloat16(a1);
    } else if (b == 128) {
        float acc = 0.f;
        #pragma unroll 8
        for (int d = 0; d < 256; d++)
            acc += qw_w[d * 256 + t] * __ldg(&kw_b[d]);
        g_u[t] = acc;
    } else if (b == 129) {
        float acc = 0.f;
        #pragma unroll 8
        for (int d = 0; d < 256; d++)
            acc += kw_w[d * 256 + t] * __ldg(&qw_b[d]);
        g_w[t] = acc;
    } else if (b == 130) {
        if (t < 32) {
            float cp = 0.f;
            #pragma unroll
            for (int m = 0; m < 8; m++)
                cp += qw_b[t + 32 * m] * kw_b[t + 32 * m];
            #pragma unroll
            for (int o = 16; o > 0; o >>= 1) cp += __shfl_xor_sync(0xffffffffu, cp, o);
            if (t == 0) g_c = cp;
        }
        __shared__ int nf[2];
        if (t < 2) nf[t] = 0;
        __syncthreads();
        const unsigned* mw = (const unsigned*)maskp;
        int bad0 = 0, bad1 = 0;
        for (int i = t; i < 16384; i += 256) {
            unsigned w = mw[i];
            if (w > 1u) bad0 = 1;
            if (w != 0u && w != 0x3F800000u) bad1 = 1;
        }
        if (bad0) nf[0] = 1;
        if (bad1) nf[1] = 1;
        __syncthreads();
        if (t == 0) g_mask_mode = nf[0] ? (nf[1] ? 0 : 2) : 1;
    } else {
        __shared__ float s[32][33];
        const int bb = b - 131;
        const int di = (bb >> 3) * 32, jj = (bb & 7) * 32;
        const int tx = t & 31, ty = t >> 5;
        #pragma unroll
        for (int u2 = 0; u2 < 4; u2++)
            s[ty + 8 * u2][tx] = vw_w[(di + ty + 8 * u2) * 256 + (jj + tx)];
        __syncthreads();
        #pragma unroll
        for (int u2 = 0; u2 < 4; u2++)
            g_WvT[(jj + ty + 8 * u2) * 256 + (di + tx)] = s[tx][ty + 8 * u2];
    }
}

// ---------------- qt_gemm: Q~ = q @ M via mma.sync bf16 ----------------
#define QG_B 65536
#define QG_TOT 99328

__global__ void __launch_bounds__(256)
qt_gemm(const float* __restrict__ q)
{
    extern __shared__ unsigned char smem[];
    unsigned char* Ab = smem;
    unsigned* Bw = (unsigned*)(smem + QG_B);
    const int t = threadIdx.x;
    const int wid = t >> 5;
    const int lane = t & 31;
    const int lq = lane & 3, lr = lane >> 2;
    const int warpm = wid & 3, warpn = wid >> 2;
    const int tile_m = blockIdx.x >> 2;
    const int tile_n = blockIdx.x & 3;

    {
        const float4* qs = (const float4*)(q + (size_t)tile_m * 128 * 256);
        #pragma unroll 4
        for (int it = 0; it < 16; it++) {
            int idx = it * 256 + t;
            int row = idx >> 5, c = idx & 31;
            float4 fa = qs[idx * 2], fb = qs[idx * 2 + 1];
            uint4 val = make_uint4(f2bf(fa.x, fa.y), f2bf(fa.z, fa.w),
                                   f2bf(fb.x, fb.y), f2bf(fb.z, fb.w));
            *(uint4*)(Ab + row * 512 + ((c ^ (row & 7)) << 4)) = val;
        }
    }
    {
        const uint4* asrc = (const uint4*)g_Aebf;
        #pragma unroll 2
        for (int it = 0; it < 8; it++) {
            int idx = it * 256 + t;
            int er = idx >> 5, c = idx & 31;
            uint4 v = asrc[(size_t)(tile_n * 64 + er) * 32 + c];
            *(uint4*)&Bw[er * 132 + c * 4] = v;
        }
    }
    __syncthreads();

    const uint32_t Abase = smem_to_u32(Ab);
    float acc[2][4][4];
    #pragma unroll
    for (int mt = 0; mt < 2; mt++)
        #pragma unroll
        for (int nt = 0; nt < 4; nt++)
            #pragma unroll
            for (int i = 0; i < 4; i++) acc[mt][nt][i] = 0.f;

    #pragma unroll 4
    for (int ks = 0; ks < 16; ks++) {
        unsigned a0[4], a1[4];
        #pragma unroll
        for (int mt = 0; mt < 2; mt++) {
            int r = warpm * 32 + mt * 16 + (lane & 15);
            int c = ks * 2 + (lane >> 4);
            uint32_t addr = Abase + r * 512 + ((c ^ (r & 7)) << 4);
            ldsm4(mt ? a1 : a0, addr);
        }
        unsigned b0[4], b1[4];
        #pragma unroll
        for (int nt = 0; nt < 4; nt++) {
            int bi = (warpn * 32 + nt * 8 + lr) * 132 + ks * 8 + lq;
            b0[nt] = Bw[bi];
            b1[nt] = Bw[bi + 4];
        }
        #pragma unroll
        for (int nt = 0; nt < 4; nt++) {
            mma16816(acc[0][nt], a0, b0[nt], b1[nt]);
            mma16816(acc[1][nt], a1, b0[nt], b1[nt]);
        }
    }

    #pragma unroll
    for (int mt = 0; mt < 2; mt++) {
        int row = tile_m * 128 + warpm * 32 + mt * 16 + lr;
        #pragma unroll
        for (int nt = 0; nt < 4; nt++) {
            int cw = tile_n * 32 + warpn * 16 + nt * 4 + lq;
            g_Qtu[(size_t)row * 128 + cw]       = f2bf(acc[mt][nt][0], acc[mt][nt][1]);
            g_Qtu[(size_t)(row + 8) * 128 + cw] = f2bf(acc[mt][nt][2], acc[mt][nt][3]);
        }
    }
}

// ---------------- fused per-pair kernel (mma.sync scores) ----------------
#define SM_QTW 65536
#define SM_A   78208
#define SM_TA  78272
#define SM_RED 79296
#define SM_TOT 79328

__device__ __forceinline__ float bsum(float v, float* red, int t) {
    __syncthreads();
    #pragma unroll
    for (int o = 16; o > 0; o >>= 1) v += __shfl_xor_sync(0xffffffffu, v, o);
    if ((t & 31) == 0) red[t >> 5] = v;
    __syncthreads();
    float r = red[0];
    #pragma unroll
    for (int i = 1; i < 8; i++) r += red[i];
    return r;
}
__device__ __forceinline__ float bmax(float v, float* red, int t) {
    __syncthreads();
    #pragma unroll
    for (int o = 16; o > 0; o >>= 1) v = fmaxf(v, __shfl_xor_sync(0xffffffffu, v, o));
    if ((t & 31) == 0) red[t >> 5] = v;
    __syncthreads();
    float r = red[0];
    #pragma unroll
    for (int i = 1; i < 8; i++) r = fmaxf(r, red[i]);
    return r;
}

__global__ void __launch_bounds__(256, 2)
fused_kernel(const float* __restrict__ q, const float* __restrict__ k,
             const float* __restrict__ v, const void* __restrict__ maskp)
{
    extern __shared__ unsigned char sm[];
    unsigned char* kb0 = sm;
    unsigned* Qtw   = (unsigned*)(sm + SM_QTW);
    float*    a_s   = (float*)(sm + SM_A);
    float*    ta_s  = (float*)(sm + SM_TA);
    float*    red_s = (float*)(sm + SM_RED);

    const int pair = blockIdx.x;
    const int t = threadIdx.x;
    const int lane = t & 31;
    const int lq = lane & 3, lr = lane >> 2;
    const float* qb = q + (size_t)pair * QL * DD;
    const float* kb = k + (size_t)pair * 256 * DD;
    const float* vb = v + (size_t)pair * 256 * DD;

    // ---- stage Qt rows 0-15, w row 16, zero rows 17-23 ----
    {
        const uint4* qtsrc = (const uint4*)(g_Qtu + (size_t)pair * 16 * 128);
        #pragma unroll
        for (int it = 0; it < 2; it++) {
            int idx = it * 256 + t;
            int row = idx >> 5, c = idx & 31;
            *(uint4*)&Qtw[row * 132 + c * 4] = qtsrc[idx];
        }
        if (t < 128) {
            float2 wv = *(const float2*)&g_w[2 * t];
            Qtw[16 * 132 + t] = f2bf(wv.x, wv.y);
        }
        for (int i = t; i < 924; i += 256) Qtw[17 * 132 + i] = 0u;
    }
    __syncthreads();

    if (t >= 128) {
        // ================= PRODUCERS (warps 4-7) =================
        const int pt = t - 128;
        #pragma unroll
        for (int s = 0; s < 4; s++) {
            unsigned char* buf = kb0 + (s & 1) * 32768;
            const float4* ks = (const float4*)(kb + (size_t)(64 * s) * 256);
            #pragma unroll 4
            for (int it = 0; it < 16; it++) {
                int idx = it * 128 + pt;
                int row = idx >> 5, c = idx & 31;
                float4 fa = ks[idx * 2], fb = ks[idx * 2 + 1];
                uint4 val = make_uint4(f2bf(fa.x, fa.y), f2bf(fa.z, fa.w),
                                       f2bf(fb.x, fb.y), f2bf(fb.z, fb.w));
                *(uint4*)(buf + row * 512 + ((c ^ (row & 7)) << 4)) = val;
            }
            // prefetch matching v slice into L2 (overlaps later phase-4 stream)
            {
                const float* vslice = vb + (size_t)(64 * s) * 256;
                #pragma unroll
                for (int m = 0; m < 4; m++)
                    PREF_L2(vslice + (pt * 4 + m) * 32);
            }
            BARX(1);
        }
        BARX(1);
    } else {
        // ================= CONSUMERS (warps 0-3) =================
        const int warpm = t >> 5;
        if (t < 32) {
            const float cc = g_c;
            for (int i = 0; i < QL; i++) {
                float p = 0.f;
                #pragma unroll
                for (int m = 0; m < 8; m++) {
                    int dd = t + 32 * m;
                    p += __ldg(&qb[i * 256 + dd]) * g_u[dd];
                }
                #pragma unroll
                for (int o = 16; o > 0; o >>= 1) p += __shfl_xor_sync(0xffffffffu, p, o);
                if (t == 0) a_s[i] = p + cc;
            }
        }
        BARX(1);

        const float a_e  = a_s[2 * lq];
        const float a_o  = a_s[2 * lq + 1];
        const float a_e8 = a_s[2 * lq + 8];
        const float a_o8 = a_s[2 * lq + 9];

        #pragma unroll
        for (int s = 0; s < 4; s++) {
            const uint32_t kbase = smem_to_u32(kb0 + (s & 1) * 32768);
            float c0[4], c1[4], cw[4];
            #pragma unroll
            for (int i = 0; i < 4; i++) { c0[i] = 0.f; c1[i] = 0.f; cw[i] = 0.f; }
            const int krow = warpm * 16 + (lane & 15);
            #pragma unroll 4
            for (int ks = 0; ks < 16; ks++) {
                unsigned a[4];
                int c = ks * 2 + (lane >> 4);
                ldsm4(a, kbase + krow * 512 + ((c ^ (krow & 7)) << 4));
                int w0 = lr * 132 + ks * 8 + lq;
                unsigned b00 = Qtw[w0],             b01 = Qtw[w0 + 4];
                unsigned b10 = Qtw[w0 + 8 * 132],   b11 = Qtw[w0 + 8 * 132 + 4];
                unsigned b20 = Qtw[w0 + 16 * 132],  b21 = Qtw[w0 + 16 * 132 + 4];
                mma16816(c0, a, b00, b01);
                mma16816(c1, a, b10, b11);
                mma16816(cw, a, b20, b21);
            }
            float mr  = fmaxf(fmaxf(c0[0] + a_e, c0[1] + a_o), fmaxf(c1[0] + a_e8, c1[1] + a_o8));
            float mr8 = fmaxf(fmaxf(c0[2] + a_e, c0[3] + a_o), fmaxf(c1[2] + a_e8, c1[3] + a_o8));
            mr  = fmaxf(mr,  __shfl_xor_sync(0xffffffffu, mr, 1));
            mr  = fmaxf(mr,  __shfl_xor_sync(0xffffffffu, mr, 2));
            mr8 = fmaxf(mr8, __shfl_xor_sync(0xffffffffu, mr8, 1));
            mr8 = fmaxf(mr8, __shfl_xor_sync(0xffffffffu, mr8, 2));
            float wkr  = __shfl_sync(0xffffffffu, cw[0], lane & ~3);
            float wkr8 = __shfl_sync(0xffffffffu, cw[2], lane & ~3);
            if (lq == 0) {
                ta_s[s * 64 + warpm * 16 + lr]     = wkr + mr;
                ta_s[s * 64 + warpm * 16 + lr + 8] = wkr8 + mr8;
            }
            BARX(1);
        }
    }

    // ---- Phase 3: normalize, mask, softmax (all 256) ----
    float cnt;
    {
        float tv = ta_s[t];
        float ss = bsum(tv * tv, red_s, t);
        float inv = rsqrtf(ss);
        const int mm = g_mask_mode;
        bool masked;
        size_t mi = (size_t)pair * 256 + t;
        if (mm == 0)      masked = ((const unsigned char*)maskp)[mi] != 0;
        else if (mm == 1) masked = ((const int*)maskp)[mi] != 0;
        else              masked = ((const float*)maskp)[mi] != 0.f;
        float x = masked ? -10.f : tv * inv;
        cnt = bsum(masked ? 0.f : 1.f, red_s, t);
        float mx = bmax(x, red_s, t);
        float ex = __expf(x - mx);
        float se = bsum(ex, red_s, t);
        float attn = (cnt == 0.f) ? 0.f : ex / se;
        ta_s[t] = attn;
        __syncthreads();
    }

    // ---- Phase 4: tvec[j=t] = sum_v attn[v] * v[v][t] ----
    {
        float acc = 0.f;
        #pragma unroll 16
        for (int vv = 0; vv < 256; vv++)
            acc += ta_s[vv] * vb[vv * 256 + t];
        g_tvec[pair * 256 + t] = acc;
        if (t == 0) g_sA[pair] = (cnt > 0.f) ? 1.f : 0.f;
    }
}

// ---------------- out stage 1: partials over 64-j chunks ----------------
// grid = 64 pair-groups x 4 col-chunks x 4 k-chunks = 1024 blocks
__global__ void __launch_bounds__(256)
out_part_kernel()
{
    __shared__ float tv[64 * 17];      // [j][r] at j*17+r
    const int t = threadIdx.x;
    const int kc = blockIdx.x & 3;
    const int cg = (blockIdx.x >> 2) & 3;
    const int pg = blockIdx.x >> 4;
    const int p0 = pg * 16;
    const int c0 = cg * 64;
    const int j0 = kc * 64;
    const int c  = c0 + (t & 63);
    const int rg = t >> 6;             // 0..3

    #pragma unroll
    for (int it = 0; it < 4; it++) {
        int idx = it * 256 + t;        // 1024 elems
        int r = idx >> 6, j = idx & 63;
        tv[j * 17 + r] = g_tvec[(p0 + r) * 256 + j0 + j];
    }
    __syncthreads();
    float acc0 = 0.f, acc1 = 0.f, acc2 = 0.f, acc3 = 0.f;
    const float* Wcol = g_WvT + (size_t)j0 * 256 + c;
    #pragma unroll 8
    for (int j = 0; j < 64; j++) {
        float wv = __ldg(&Wcol[j * 256]);
        const float* T = &tv[j * 17];
        acc0 += T[rg]      * wv;
        acc1 += T[rg + 4]  * wv;
        acc2 += T[rg + 8]  * wv;
        acc3 += T[rg + 12] * wv;
    }
    float* op = g_opart + (size_t)kc * PAIRS * 256;
    op[(size_t)(p0 + rg)      * 256 + c] = acc0;
    op[(size_t)(p0 + rg + 4)  * 256 + c] = acc1;
    op[(size_t)(p0 + rg + 8)  * 256 + c] = acc2;
    op[(size_t)(p0 + rg + 12) * 256 + c] = acc3;
}

// ---------------- out stage 2: sum partials + bias ----------------
__global__ void __launch_bounds__(256)
out_sum_kernel(const float* __restrict__ vw_b, float* __restrict__ out)
{
    const int t = threadIdx.x;
    const int o0 = blockIdx.x * 1024 + t;   // 4 outputs per thread, stride 256
    #pragma unroll
    for (int it = 0; it < 4; it++) {
        int o = o0 + it * 256;
        int row = o >> 8, c = o & 255;
        float s = g_opart[o] + g_opart[o + PAIRS * 256]
                + g_opart[o + 2 * PAIRS * 256] + g_opart[o + 3 * PAIRS * 256];
        out[o] = s + g_sA[row] * __ldg(&vw_b[c]);
    }
}

extern "C" void kernel_launch(void* const* d_in, const int* in_sizes, int n_in,
                              void* d_out, int out_size)
{
    const float* q    = (const float*)d_in[0];
    const float* k    = (const float*)d_in[1];
    const float* v    = (const float*)d_in[2];
    const void*  m    = d_in[3];
    const float* qw_w = (const float*)d_in[4];
    const float* qw_b = (const float*)d_in[5];
    const float* kw_w = (const float*)d_in[6];
    const float* kw_b = (const float*)d_in[7];
    const float* vw_w = (const float*)d_in[8];
    const float* vw_b = (const float*)d_in[9];
    float* out = (float*)d_out;
    (void)in_sizes; (void)n_in; (void)out_size;

    cudaFuncSetAttribute(qt_gemm, cudaFuncAttributeMaxDynamicSharedMemorySize, QG_TOT);
    cudaFuncSetAttribute(fused_kernel, cudaFuncAttributeMaxDynamicSharedMemorySize, SM_TOT);

    setup_kernel<<<195, 256>>>(qw_w, qw_b, kw_w, kw_b, vw_w, m);
    qt_gemm<<<512, 256, QG_TOT>>>(q);
    fused_kernel<<<PAIRS, 256, SM_TOT>>>(q, k, v, m);
    out_part_kernel<<<1024, 256>>>();
    out_sum_kernel<<<256, 256>>>(vw_b, out);
}

// round 12
// speedup vs baseline: 2.2875x; 1.0737x over previous
#include <cuda_runtime.h>
#include <cuda_bf16.h>
#include <cstdint>

typedef unsigned long long ull;

#define PAIRS 1024
#define DD 256
#define QL 16

// ---------------- persistent scratch / precomputed ----------------
__device__ __nv_bfloat16 g_Aebf[256 * 256];  // M^T: [e][d] = M[d][e], bf16 (MMA B operand)
__device__ float    g_WvT[256 * 256];        // WvT[j][d] = vw_w[d][j]
__device__ float    g_u[256];
__device__ float    g_w[256];
__device__ float    g_c;
__device__ int      g_mask_mode;             // 0=u8 bool, 1=int32, 2=float32
__device__ unsigned g_Qtu[16384 * 128];      // Q-tilde bf16x2 words
__device__ float    g_attn[PAIRS * 256];     // softmax weights per pair
__device__ float    g_tvh[2 * PAIRS * 256];  // attn.v partials per v-half
__device__ float    g_sA[PAIRS];             // 1 if any unmasked else 0
__device__ float    g_opart[4 * PAIRS * 256];// split-K partials [kc][row][c]

__device__ __forceinline__ unsigned f2bf(float a, float b) {
    __nv_bfloat162 h = __floats2bfloat162_rn(a, b);
    return *reinterpret_cast<unsigned*>(&h);
}
__device__ __forceinline__ uint32_t smem_to_u32(const void* p) {
    uint32_t a;
    asm("{ .reg .u64 tmp; cvta.to.shared.u64 tmp, %1; cvt.u32.u64 %0, tmp; }" : "=r"(a) : "l"(p));
    return a;
}
__device__ __forceinline__ void ldsm4(unsigned* r, uint32_t addr) {
    asm volatile("ldmatrix.sync.aligned.m8n8.x4.shared.b16 {%0,%1,%2,%3}, [%4];"
        : "=r"(r[0]), "=r"(r[1]), "=r"(r[2]), "=r"(r[3]) : "r"(addr));
}
__device__ __forceinline__ void mma16816(float* c, const unsigned* a, unsigned b0, unsigned b1) {
    asm volatile(
        "mma.sync.aligned.m16n8k16.row.col.f32.bf16.bf16.f32 "
        "{%0,%1,%2,%3}, {%4,%5,%6,%7}, {%8,%9}, {%0,%1,%2,%3};"
        : "+f"(c[0]), "+f"(c[1]), "+f"(c[2]), "+f"(c[3])
        : "r"(a[0]), "r"(a[1]), "r"(a[2]), "r"(a[3]), "r"(b0), "r"(b1));
}
#define BARX(id) asm volatile("bar.sync %0, 256;" :: "r"(id) : "memory")

// ---------------- setup kernel ----------------
__global__ void setup_kernel(const float* __restrict__ qw_w, const float* __restrict__ qw_b,
                             const float* __restrict__ kw_w, const float* __restrict__ kw_b,
                             const float* __restrict__ vw_w, const void* __restrict__ maskp)
{
    const int b = blockIdx.x;
    const int t = threadIdx.x;
    if (b < 128) {
        const int e0 = b * 2;
        float a0 = 0.f, a1 = 0.f;
        for (int cb = 0; cb < 256; cb += 8) {
            float qv[8]; float2 kv[8];
            #pragma unroll
            for (int m = 0; m < 8; m++) qv[m] = qw_w[(cb + m) * 256 + t];
            #pragma unroll
            for (int m = 0; m < 8; m++) kv[m] = *(const float2*)&kw_w[(cb + m) * 256 + e0];
            #pragma unroll
            for (int m = 0; m < 8; m++) { a0 += qv[m] * kv[m].x; a1 += qv[m] * kv[m].y; }
        }
        g_Aebf[(e0 + 0) * 256 + t] = __float2bfloat16(a0);
        g_Aebf[(e0 + 1) * 256 + t] = __float2bfloat16(a1);
    } else if (b == 128) {
        float acc = 0.f;
        #pragma unroll 8
        for (int d = 0; d < 256; d++)
            acc += qw_w[d * 256 + t] * __ldg(&kw_b[d]);
        g_u[t] = acc;
    } else if (b == 129) {
        float acc = 0.f;
        #pragma unroll 8
        for (int d = 0; d < 256; d++)
            acc += kw_w[d * 256 + t] * __ldg(&qw_b[d]);
        g_w[t] = acc;
    } else if (b == 130) {
        if (t < 32) {
            float cp = 0.f;
            #pragma unroll
            for (int m = 0; m < 8; m++)
                cp += qw_b[t + 32 * m] * kw_b[t + 32 * m];
            #pragma unroll
            for (int o = 16; o > 0; o >>= 1) cp += __shfl_xor_sync(0xffffffffu, cp, o);
            if (t == 0) g_c = cp;
        }
        __shared__ int nf[2];
        if (t < 2) nf[t] = 0;
        __syncthreads();
        const unsigned* mw = (const unsigned*)maskp;
        int bad0 = 0, bad1 = 0;
        for (int i = t; i < 16384; i += 256) {
            unsigned w = mw[i];
            if (w > 1u) bad0 = 1;
            if (w != 0u && w != 0x3F800000u) bad1 = 1;
        }
        if (bad0) nf[0] = 1;
        if (bad1) nf[1] = 1;
        __syncthreads();
        if (t == 0) g_mask_mode = nf[0] ? (nf[1] ? 0 : 2) : 1;
    } else {
        __shared__ float s[32][33];
        const int bb = b - 131;
        const int di = (bb >> 3) * 32, jj = (bb & 7) * 32;
        const int tx = t & 31, ty = t >> 5;
        #pragma unroll
        for (int u2 = 0; u2 < 4; u2++)
            s[ty + 8 * u2][tx] = vw_w[(di + ty + 8 * u2) * 256 + (jj + tx)];
        __syncthreads();
        #pragma unroll
        for (int u2 = 0; u2 < 4; u2++)
            g_WvT[(jj + ty + 8 * u2) * 256 + (di + tx)] = s[tx][ty + 8 * u2];
    }
}

// ---------------- qt_gemm: Q~ = q @ M via mma.sync bf16 ----------------
#define QG_B 65536
#define QG_TOT 99328

__global__ void __launch_bounds__(256)
qt_gemm(const float* __restrict__ q)
{
    extern __shared__ unsigned char smem[];
    unsigned char* Ab = smem;
    unsigned* Bw = (unsigned*)(smem + QG_B);
    const int t = threadIdx.x;
    const int wid = t >> 5;
    const int lane = t & 31;
    const int lq = lane & 3, lr = lane >> 2;
    const int warpm = wid & 3, warpn = wid >> 2;
    const int tile_m = blockIdx.x >> 2;
    const int tile_n = blockIdx.x & 3;

    {
        const float4* qs = (const float4*)(q + (size_t)tile_m * 128 * 256);
        #pragma unroll 4
        for (int it = 0; it < 16; it++) {
            int idx = it * 256 + t;
            int row = idx >> 5, c = idx & 31;
            float4 fa = qs[idx * 2], fb = qs[idx * 2 + 1];
            uint4 val = make_uint4(f2bf(fa.x, fa.y), f2bf(fa.z, fa.w),
                                   f2bf(fb.x, fb.y), f2bf(fb.z, fb.w));
            *(uint4*)(Ab + row * 512 + ((c ^ (row & 7)) << 4)) = val;
        }
    }
    {
        const uint4* asrc = (const uint4*)g_Aebf;
        #pragma unroll 2
        for (int it = 0; it < 8; it++) {
            int idx = it * 256 + t;
            int er = idx >> 5, c = idx & 31;
            uint4 v = asrc[(size_t)(tile_n * 64 + er) * 32 + c];
            *(uint4*)&Bw[er * 132 + c * 4] = v;
        }
    }
    __syncthreads();

    const uint32_t Abase = smem_to_u32(Ab);
    float acc[2][4][4];
    #pragma unroll
    for (int mt = 0; mt < 2; mt++)
        #pragma unroll
        for (int nt = 0; nt < 4; nt++)
            #pragma unroll
            for (int i = 0; i < 4; i++) acc[mt][nt][i] = 0.f;

    #pragma unroll 4
    for (int ks = 0; ks < 16; ks++) {
        unsigned a0[4], a1[4];
        #pragma unroll
        for (int mt = 0; mt < 2; mt++) {
            int r = warpm * 32 + mt * 16 + (lane & 15);
            int c = ks * 2 + (lane >> 4);
            uint32_t addr = Abase + r * 512 + ((c ^ (r & 7)) << 4);
            ldsm4(mt ? a1 : a0, addr);
        }
        unsigned b0[4], b1[4];
        #pragma unroll
        for (int nt = 0; nt < 4; nt++) {
            int bi = (warpn * 32 + nt * 8 + lr) * 132 + ks * 8 + lq;
            b0[nt] = Bw[bi];
            b1[nt] = Bw[bi + 4];
        }
        #pragma unroll
        for (int nt = 0; nt < 4; nt++) {
            mma16816(acc[0][nt], a0, b0[nt], b1[nt]);
            mma16816(acc[1][nt], a1, b0[nt], b1[nt]);
        }
    }

    #pragma unroll
    for (int mt = 0; mt < 2; mt++) {
        int row = tile_m * 128 + warpm * 32 + mt * 16 + lr;
        #pragma unroll
        for (int nt = 0; nt < 4; nt++) {
            int cw = tile_n * 32 + warpn * 16 + nt * 4 + lq;
            g_Qtu[(size_t)row * 128 + cw]       = f2bf(acc[mt][nt][0], acc[mt][nt][1]);
            g_Qtu[(size_t)(row + 8) * 128 + cw] = f2bf(acc[mt][nt][2], acc[mt][nt][3]);
        }
    }
}

// ---------------- fused per-pair kernel: scores + softmax only ----------------
#define SM_QTW 65536
#define SM_A   78208
#define SM_TA  78272
#define SM_RED 79296
#define SM_TOT 79328

__device__ __forceinline__ float bsum(float v, float* red, int t) {
    __syncthreads();
    #pragma unroll
    for (int o = 16; o > 0; o >>= 1) v += __shfl_xor_sync(0xffffffffu, v, o);
    if ((t & 31) == 0) red[t >> 5] = v;
    __syncthreads();
    float r = red[0];
    #pragma unroll
    for (int i = 1; i < 8; i++) r += red[i];
    return r;
}
__device__ __forceinline__ float bmax(float v, float* red, int t) {
    __syncthreads();
    #pragma unroll
    for (int o = 16; o > 0; o >>= 1) v = fmaxf(v, __shfl_xor_sync(0xffffffffu, v, o));
    if ((t & 31) == 0) red[t >> 5] = v;
    __syncthreads();
    float r = red[0];
    #pragma unroll
    for (int i = 1; i < 8; i++) r = fmaxf(r, red[i]);
    return r;
}

__global__ void __launch_bounds__(256, 2)
fused_kernel(const float* __restrict__ q, const float* __restrict__ k,
             const void* __restrict__ maskp)
{
    extern __shared__ unsigned char sm[];
    unsigned char* kb0 = sm;
    unsigned* Qtw   = (unsigned*)(sm + SM_QTW);
    float*    a_s   = (float*)(sm + SM_A);
    float*    ta_s  = (float*)(sm + SM_TA);
    float*    red_s = (float*)(sm + SM_RED);

    const int pair = blockIdx.x;
    const int t = threadIdx.x;
    const int lane = t & 31;
    const int lq = lane & 3, lr = lane >> 2;
    const float* qb = q + (size_t)pair * QL * DD;
    const float* kb = k + (size_t)pair * 256 * DD;

    // ---- stage Qt rows 0-15, w row 16, zero rows 17-23 ----
    {
        const uint4* qtsrc = (const uint4*)(g_Qtu + (size_t)pair * 16 * 128);
        #pragma unroll
        for (int it = 0; it < 2; it++) {
            int idx = it * 256 + t;
            int row = idx >> 5, c = idx & 31;
            *(uint4*)&Qtw[row * 132 + c * 4] = qtsrc[idx];
        }
        if (t < 128) {
            float2 wv = *(const float2*)&g_w[2 * t];
            Qtw[16 * 132 + t] = f2bf(wv.x, wv.y);
        }
        for (int i = t; i < 924; i += 256) Qtw[17 * 132 + i] = 0u;
    }
    __syncthreads();

    if (t >= 128) {
        // ================= PRODUCERS (warps 4-7) =================
        const int pt = t - 128;
        #pragma unroll
        for (int s = 0; s < 4; s++) {
            unsigned char* buf = kb0 + (s & 1) * 32768;
            const float4* ks = (const float4*)(kb + (size_t)(64 * s) * 256);
            #pragma unroll 4
            for (int it = 0; it < 16; it++) {
                int idx = it * 128 + pt;
                int row = idx >> 5, c = idx & 31;
                float4 fa = ks[idx * 2], fb = ks[idx * 2 + 1];
                uint4 val = make_uint4(f2bf(fa.x, fa.y), f2bf(fa.z, fa.w),
                                       f2bf(fb.x, fb.y), f2bf(fb.z, fb.w));
                *(uint4*)(buf + row * 512 + ((c ^ (row & 7)) << 4)) = val;
            }
            BARX(1);
        }
        BARX(1);
    } else {
        // ================= CONSUMERS (warps 0-3) =================
        const int warpm = t >> 5;
        if (t < 32) {
            const float cc = g_c;
            for (int i = 0; i < QL; i++) {
                float p = 0.f;
                #pragma unroll
                for (int m = 0; m < 8; m++) {
                    int dd = t + 32 * m;
                    p += __ldg(&qb[i * 256 + dd]) * g_u[dd];
                }
                #pragma unroll
                for (int o = 16; o > 0; o >>= 1) p += __shfl_xor_sync(0xffffffffu, p, o);
                if (t == 0) a_s[i] = p + cc;
            }
        }
        BARX(1);

        const float a_e  = a_s[2 * lq];
        const float a_o  = a_s[2 * lq + 1];
        const float a_e8 = a_s[2 * lq + 8];
        const float a_o8 = a_s[2 * lq + 9];

        #pragma unroll
        for (int s = 0; s < 4; s++) {
            const uint32_t kbase = smem_to_u32(kb0 + (s & 1) * 32768);
            float c0[4], c1[4], cw[4];
            #pragma unroll
            for (int i = 0; i < 4; i++) { c0[i] = 0.f; c1[i] = 0.f; cw[i] = 0.f; }
            const int krow = warpm * 16 + (lane & 15);
            #pragma unroll 4
            for (int ks = 0; ks < 16; ks++) {
                unsigned a[4];
                int c = ks * 2 + (lane >> 4);
                ldsm4(a, kbase + krow * 512 + ((c ^ (krow & 7)) << 4));
                int w0 = lr * 132 + ks * 8 + lq;
                unsigned b00 = Qtw[w0],             b01 = Qtw[w0 + 4];
                unsigned b10 = Qtw[w0 + 8 * 132],   b11 = Qtw[w0 + 8 * 132 + 4];
                unsigned b20 = Qtw[w0 + 16 * 132],  b21 = Qtw[w0 + 16 * 132 + 4];
                mma16816(c0, a, b00, b01);
                mma16816(c1, a, b10, b11);
                mma16816(cw, a, b20, b21);
            }
            float mr  = fmaxf(fmaxf(c0[0] + a_e, c0[1] + a_o), fmaxf(c1[0] + a_e8, c1[1] + a_o8));
            float mr8 = fmaxf(fmaxf(c0[2] + a_e, c0[3] + a_o), fmaxf(c1[2] + a_e8, c1[3] + a_o8));
            mr  = fmaxf(mr,  __shfl_xor_sync(0xffffffffu, mr, 1));
            mr  = fmaxf(mr,  __shfl_xor_sync(0xffffffffu, mr, 2));
            mr8 = fmaxf(mr8, __shfl_xor_sync(0xffffffffu, mr8, 1));
            mr8 = fmaxf(mr8, __shfl_xor_sync(0xffffffffu, mr8, 2));
            float wkr  = __shfl_sync(0xffffffffu, cw[0], lane & ~3);
            float wkr8 = __shfl_sync(0xffffffffu, cw[2], lane & ~3);
            if (lq == 0) {
                ta_s[s * 64 + warpm * 16 + lr]     = wkr + mr;
                ta_s[s * 64 + warpm * 16 + lr + 8] = wkr8 + mr8;
            }
            BARX(1);
        }
    }

    // ---- normalize, mask, softmax (all 256); write attn + sA ----
    {
        float tv = ta_s[t];
        float ss = bsum(tv * tv, red_s, t);
        float inv = rsqrtf(ss);
        const int mm = g_mask_mode;
        bool masked;
        size_t mi = (size_t)pair * 256 + t;
        if (mm == 0)      masked = ((const unsigned char*)maskp)[mi] != 0;
        else if (mm == 1) masked = ((const int*)maskp)[mi] != 0;
        else              masked = ((const float*)maskp)[mi] != 0.f;
        float x = masked ? -10.f : tv * inv;
        float cnt = bsum(masked ? 0.f : 1.f, red_s, t);
        float mx = bmax(x, red_s, t);
        float ex = __expf(x - mx);
        float se = bsum(ex, red_s, t);
        float attn = (cnt == 0.f) ? 0.f : ex / se;
        g_attn[(size_t)pair * 256 + t] = attn;
        if (t == 0) g_sA[pair] = (cnt > 0.f) ? 1.f : 0.f;
    }
}

// ---------------- av_kernel: tvec partials, pure v stream ----------------
// grid = 1024 pairs x 2 v-halves
__global__ void __launch_bounds__(256)
av_kernel(const float* __restrict__ v)
{
    __shared__ float at[128];
    const int t = threadIdx.x;
    const int pair = blockIdx.x >> 1;
    const int half = blockIdx.x & 1;
    if (t < 128) at[t] = g_attn[(size_t)pair * 256 + half * 128 + t];
    __syncthreads();
    const float* vb = v + ((size_t)pair * 256 + half * 128) * 256;
    float acc = 0.f;
    #pragma unroll 16
    for (int r = 0; r < 128; r++)
        acc += at[r] * vb[r * 256 + t];
    g_tvh[(size_t)half * PAIRS * 256 + (size_t)pair * 256 + t] = acc;
}

// ---------------- out stage 1: partials over 64-j chunks ----------------
__global__ void __launch_bounds__(256)
out_part_kernel()
{
    __shared__ float tv[64 * 17];
    const int t = threadIdx.x;
    const int kc = blockIdx.x & 3;
    const int cg = (blockIdx.x >> 2) & 3;
    const int pg = blockIdx.x >> 4;
    const int p0 = pg * 16;
    const int c0 = cg * 64;
    const int j0 = kc * 64;
    const int c  = c0 + (t & 63);
    const int rg = t >> 6;

    #pragma unroll
    for (int it = 0; it < 4; it++) {
        int idx = it * 256 + t;
        int r = idx >> 6, j = idx & 63;
        size_t e = (size_t)(p0 + r) * 256 + j0 + j;
        tv[j * 17 + r] = g_tvh[e] + g_tvh[(size_t)PAIRS * 256 + e];
    }
    __syncthreads();
    float acc0 = 0.f, acc1 = 0.f, acc2 = 0.f, acc3 = 0.f;
    const float* Wcol = g_WvT + (size_t)j0 * 256 + c;
    #pragma unroll 8
    for (int j = 0; j < 64; j++) {
        float wv = __ldg(&Wcol[j * 256]);
        const float* T = &tv[j * 17];
        acc0 += T[rg]      * wv;
        acc1 += T[rg + 4]  * wv;
        acc2 += T[rg + 8]  * wv;
        acc3 += T[rg + 12] * wv;
    }
    float* op = g_opart + (size_t)kc * PAIRS * 256;
    op[(size_t)(p0 + rg)      * 256 + c] = acc0;
    op[(size_t)(p0 + rg + 4)  * 256 + c] = acc1;
    op[(size_t)(p0 + rg + 8)  * 256 + c] = acc2;
    op[(size_t)(p0 + rg + 12) * 256 + c] = acc3;
}

// ---------------- out stage 2: sum partials + bias ----------------
__global__ void __launch_bounds__(256)
out_sum_kernel(const float* __restrict__ vw_b, float* __restrict__ out)
{
    const int t = threadIdx.x;
    const int o0 = blockIdx.x * 1024 + t;
    #pragma unroll
    for (int it = 0; it < 4; it++) {
        int o = o0 + it * 256;
        int row = o >> 8, c = o & 255;
        float s = g_opart[o] + g_opart[o + PAIRS * 256]
                + g_opart[o + 2 * PAIRS * 256] + g_opart[o + 3 * PAIRS * 256];
        out[o] = s + g_sA[row] * __ldg(&vw_b[c]);
    }
}

extern "C" void kernel_launch(void* const* d_in, const int* in_sizes, int n_in,
                              void* d_out, int out_size)
{
    const float* q    = (const float*)d_in[0];
    const float* k    = (const float*)d_in[1];
    const float* v    = (const float*)d_in[2];
    const void*  m    = d_in[3];
    const float* qw_w = (const float*)d_in[4];
    const float* qw_b = (const float*)d_in[5];
    const float* kw_w = (const float*)d_in[6];
    const float* kw_b = (const float*)d_in[7];
    const float* vw_w = (const float*)d_in[8];
    const float* vw_b = (const float*)d_in[9];
    float* out = (float*)d_out;
    (void)in_sizes; (void)n_in; (void)out_size;

    cudaFuncSetAttribute(qt_gemm, cudaFuncAttributeMaxDynamicSharedMemorySize, QG_TOT);
    cudaFuncSetAttribute(fused_kernel, cudaFuncAttributeMaxDynamicSharedMemorySize, SM_TOT);

    setup_kernel<<<195, 256>>>(qw_w, qw_b, kw_w, kw_b, vw_w, m);
    qt_gemm<<<512, 256, QG_TOT>>>(q);
    fused_kernel<<<PAIRS, 256, SM_TOT>>>(q, k, m);
    av_kernel<<<2048, 256>>>(v);
    out_part_kernel<<<1024, 256>>>();
    out_sum_kernel<<<256, 256>>>(vw_b, out);
}

// round 13
// speedup vs baseline: 2.3878x; 1.0439x over previous
#include <cuda_runtime.h>
#include <cuda_bf16.h>
#include <cstdint>

typedef unsigned long long ull;

#define PAIRS 1024
#define DD 256
#define QL 16

// ---------------- persistent scratch / precomputed ----------------
__device__ __nv_bfloat16 g_Aebf[256 * 256];  // M^T: [e][d] = M[d][e], bf16 (MMA B operand)
__device__ float    g_WvT[256 * 256];        // WvT[j][d] = vw_w[d][j]
__device__ float    g_u[256];
__device__ float    g_w[256];
__device__ float    g_c;
__device__ int      g_mask_mode;             // 0=u8 bool, 1=int32, 2=float32
__device__ unsigned g_Qtu[16384 * 128];      // Q-tilde bf16x2 words
__device__ float    g_attn[PAIRS * 256];     // softmax weights per pair
__device__ float    g_tvh[2 * PAIRS * 256];  // attn.v partials per v-half
__device__ float    g_sA[PAIRS];             // 1 if any unmasked else 0
__device__ float    g_opart[4 * PAIRS * 256];// split-K partials [kc][row][c]

__device__ __forceinline__ unsigned f2bf(float a, float b) {
    __nv_bfloat162 h = __floats2bfloat162_rn(a, b);
    return *reinterpret_cast<unsigned*>(&h);
}
__device__ __forceinline__ uint32_t smem_to_u32(const void* p) {
    uint32_t a;
    asm("{ .reg .u64 tmp; cvta.to.shared.u64 tmp, %1; cvt.u32.u64 %0, tmp; }" : "=r"(a) : "l"(p));
    return a;
}
__device__ __forceinline__ void ldsm4(unsigned* r, uint32_t addr) {
    asm volatile("ldmatrix.sync.aligned.m8n8.x4.shared.b16 {%0,%1,%2,%3}, [%4];"
        : "=r"(r[0]), "=r"(r[1]), "=r"(r[2]), "=r"(r[3]) : "r"(addr));
}
__device__ __forceinline__ void mma16816(float* c, const unsigned* a, unsigned b0, unsigned b1) {
    asm volatile(
        "mma.sync.aligned.m16n8k16.row.col.f32.bf16.bf16.f32 "
        "{%0,%1,%2,%3}, {%4,%5,%6,%7}, {%8,%9}, {%0,%1,%2,%3};"
        : "+f"(c[0]), "+f"(c[1]), "+f"(c[2]), "+f"(c[3])
        : "r"(a[0]), "r"(a[1]), "r"(a[2]), "r"(a[3]), "r"(b0), "r"(b1));
}

// ---------------- setup kernel ----------------
__global__ void setup_kernel(const float* __restrict__ qw_w, const float* __restrict__ qw_b,
                             const float* __restrict__ kw_w, const float* __restrict__ kw_b,
                             const float* __restrict__ vw_w, const void* __restrict__ maskp)
{
    const int b = blockIdx.x;
    const int t = threadIdx.x;
    if (b < 128) {
        const int e0 = b * 2;
        float a0 = 0.f, a1 = 0.f;
        for (int cb = 0; cb < 256; cb += 8) {
            float qv[8]; float2 kv[8];
            #pragma unroll
            for (int m = 0; m < 8; m++) qv[m] = qw_w[(cb + m) * 256 + t];
            #pragma unroll
            for (int m = 0; m < 8; m++) kv[m] = *(const float2*)&kw_w[(cb + m) * 256 + e0];
            #pragma unroll
            for (int m = 0; m < 8; m++) { a0 += qv[m] * kv[m].x; a1 += qv[m] * kv[m].y; }
        }
        g_Aebf[(e0 + 0) * 256 + t] = __float2bfloat16(a0);
        g_Aebf[(e0 + 1) * 256 + t] = __float2bfloat16(a1);
    } else if (b == 128) {
        float acc = 0.f;
        #pragma unroll 8
        for (int d = 0; d < 256; d++)
            acc += qw_w[d * 256 + t] * __ldg(&kw_b[d]);
        g_u[t] = acc;
    } else if (b == 129) {
        float acc = 0.f;
        #pragma unroll 8
        for (int d = 0; d < 256; d++)
            acc += kw_w[d * 256 + t] * __ldg(&qw_b[d]);
        g_w[t] = acc;
    } else if (b == 130) {
        if (t < 32) {
            float cp = 0.f;
            #pragma unroll
            for (int m = 0; m < 8; m++)
                cp += qw_b[t + 32 * m] * kw_b[t + 32 * m];
            #pragma unroll
            for (int o = 16; o > 0; o >>= 1) cp += __shfl_xor_sync(0xffffffffu, cp, o);
            if (t == 0) g_c = cp;
        }
        __shared__ int nf[2];
        if (t < 2) nf[t] = 0;
        __syncthreads();
        const unsigned* mw = (const unsigned*)maskp;
        int bad0 = 0, bad1 = 0;
        for (int i = t; i < 16384; i += 256) {
            unsigned w = mw[i];
            if (w > 1u) bad0 = 1;
            if (w != 0u && w != 0x3F800000u) bad1 = 1;
        }
        if (bad0) nf[0] = 1;
        if (bad1) nf[1] = 1;
        __syncthreads();
        if (t == 0) g_mask_mode = nf[0] ? (nf[1] ? 0 : 2) : 1;
    } else {
        __shared__ float s[32][33];
        const int bb = b - 131;
        const int di = (bb >> 3) * 32, jj = (bb & 7) * 32;
        const int tx = t & 31, ty = t >> 5;
        #pragma unroll
        for (int u2 = 0; u2 < 4; u2++)
            s[ty + 8 * u2][tx] = vw_w[(di + ty + 8 * u2) * 256 + (jj + tx)];
        __syncthreads();
        #pragma unroll
        for (int u2 = 0; u2 < 4; u2++)
            g_WvT[(jj + ty + 8 * u2) * 256 + (di + tx)] = s[tx][ty + 8 * u2];
    }
}

// ---------------- qt_gemm: Q~ = q @ M via mma.sync bf16 ----------------
#define QG_B 65536
#define QG_TOT 99328

__global__ void __launch_bounds__(256, 2)
qt_gemm(const float* __restrict__ q)
{
    extern __shared__ unsigned char smem[];
    unsigned char* Ab = smem;
    unsigned* Bw = (unsigned*)(smem + QG_B);
    const int t = threadIdx.x;
    const int wid = t >> 5;
    const int lane = t & 31;
    const int lq = lane & 3, lr = lane >> 2;
    const int warpm = wid & 3, warpn = wid >> 2;
    const int tile_m = blockIdx.x >> 2;
    const int tile_n = blockIdx.x & 3;

    {
        const float4* qs = (const float4*)(q + (size_t)tile_m * 128 * 256);
        #pragma unroll 4
        for (int it = 0; it < 16; it++) {
            int idx = it * 256 + t;
            int row = idx >> 5, c = idx & 31;
            float4 fa = qs[idx * 2], fb = qs[idx * 2 + 1];
            uint4 val = make_uint4(f2bf(fa.x, fa.y), f2bf(fa.z, fa.w),
                                   f2bf(fb.x, fb.y), f2bf(fb.z, fb.w));
            *(uint4*)(Ab + row * 512 + ((c ^ (row & 7)) << 4)) = val;
        }
    }
    {
        const uint4* asrc = (const uint4*)g_Aebf;
        #pragma unroll 2
        for (int it = 0; it < 8; it++) {
            int idx = it * 256 + t;
            int er = idx >> 5, c = idx & 31;
            uint4 v = asrc[(size_t)(tile_n * 64 + er) * 32 + c];
            *(uint4*)&Bw[er * 132 + c * 4] = v;
        }
    }
    __syncthreads();

    const uint32_t Abase = smem_to_u32(Ab);
    float acc[2][4][4];
    #pragma unroll
    for (int mt = 0; mt < 2; mt++)
        #pragma unroll
        for (int nt = 0; nt < 4; nt++)
            #pragma unroll
            for (int i = 0; i < 4; i++) acc[mt][nt][i] = 0.f;

    #pragma unroll 4
    for (int ks = 0; ks < 16; ks++) {
        unsigned a0[4], a1[4];
        #pragma unroll
        for (int mt = 0; mt < 2; mt++) {
            int r = warpm * 32 + mt * 16 + (lane & 15);
            int c = ks * 2 + (lane >> 4);
            uint32_t addr = Abase + r * 512 + ((c ^ (r & 7)) << 4);
            ldsm4(mt ? a1 : a0, addr);
        }
        unsigned b0[4], b1[4];
        #pragma unroll
        for (int nt = 0; nt < 4; nt++) {
            int bi = (warpn * 32 + nt * 8 + lr) * 132 + ks * 8 + lq;
            b0[nt] = Bw[bi];
            b1[nt] = Bw[bi + 4];
        }
        #pragma unroll
        for (int nt = 0; nt < 4; nt++) {
            mma16816(acc[0][nt], a0, b0[nt], b1[nt]);
            mma16816(acc[1][nt], a1, b0[nt], b1[nt]);
        }
    }

    #pragma unroll
    for (int mt = 0; mt < 2; mt++) {
        int row = tile_m * 128 + warpm * 32 + mt * 16 + lr;
        #pragma unroll
        for (int nt = 0; nt < 4; nt++) {
            int cw = tile_n * 32 + warpn * 16 + nt * 4 + lq;
            g_Qtu[(size_t)row * 128 + cw]       = f2bf(acc[mt][nt][0], acc[mt][nt][1]);
            g_Qtu[(size_t)(row + 8) * 128 + cw] = f2bf(acc[mt][nt][2], acc[mt][nt][3]);
        }
    }
}

// ---------------- fused kernel: all-warp pipelined scores + softmax ----------------
// smem (bytes):
//   [0,     32768)  kbuf0 : 64 rows x 512B bf16, chunk^(r&7)
//   [32768, 65536)  kbuf1
//   [65536, 78208)  Qtw   : 24 rows x 132 words; rows 0-15 Qt, 16 w, 17-23 zero
//   [78208, 84864)  cred  : C partials, (mt*32+lane)*13 floats
//   [84864, 84928)  a_s   : 16 floats
//   [84928, 85952)  ta_s  : 256 floats
//   [85952, 85984)  red   : 8 floats
#define SM_QTW 65536
#define SM_CRED 78208
#define SM_A   84864
#define SM_TA  84928
#define SM_RED 85952
#define SM_TOT 85984

__device__ __forceinline__ float bsum(float v, float* red, int t) {
    __syncthreads();
    #pragma unroll
    for (int o = 16; o > 0; o >>= 1) v += __shfl_xor_sync(0xffffffffu, v, o);
    if ((t & 31) == 0) red[t >> 5] = v;
    __syncthreads();
    float r = red[0];
    #pragma unroll
    for (int i = 1; i < 8; i++) r += red[i];
    return r;
}
__device__ __forceinline__ float bmax(float v, float* red, int t) {
    __syncthreads();
    #pragma unroll
    for (int o = 16; o > 0; o >>= 1) v = fmaxf(v, __shfl_xor_sync(0xffffffffu, v, o));
    if ((t & 31) == 0) red[t >> 5] = v;
    __syncthreads();
    float r = red[0];
    #pragma unroll
    for (int i = 1; i < 8; i++) r = fmaxf(r, red[i]);
    return r;
}

__global__ void __launch_bounds__(256, 2)
fused_kernel(const float* __restrict__ q, const float* __restrict__ k,
             const void* __restrict__ maskp)
{
    extern __shared__ unsigned char sm[];
    unsigned char* kb0 = sm;
    unsigned* Qtw   = (unsigned*)(sm + SM_QTW);
    float*    cred  = (float*)(sm + SM_CRED);
    float*    a_s   = (float*)(sm + SM_A);
    float*    ta_s  = (float*)(sm + SM_TA);
    float*    red_s = (float*)(sm + SM_RED);

    const int pair = blockIdx.x;
    const int t = threadIdx.x;
    const int lane = t & 31;
    const int lq = lane & 3, lr = lane >> 2;
    const int w  = t >> 5;
    const int mt = w >> 1;      // m-tile 0..3 (16 rows each within 64-row stage)
    const int kh = w & 1;       // ks-half
    const float* qb = q + (size_t)pair * QL * DD;
    const float* kb = k + (size_t)pair * 256 * DD;

    // ---- stage Qt rows 0-15, w row 16, zero rows 17-23 ----
    {
        const uint4* qtsrc = (const uint4*)(g_Qtu + (size_t)pair * 16 * 128);
        #pragma unroll
        for (int it = 0; it < 2; it++) {
            int idx = it * 256 + t;
            int row = idx >> 5, c = idx & 31;
            *(uint4*)&Qtw[row * 132 + c * 4] = qtsrc[idx];
        }
        if (t < 128) {
            float2 wv = *(const float2*)&g_w[2 * t];
            Qtw[16 * 132 + t] = f2bf(wv.x, wv.y);
        }
        for (int i = t; i < 924; i += 256) Qtw[17 * 132 + i] = 0u;
    }

    // ---- load stage 0 into regs (all 256 threads) ----
    float4 R[16];
    {
        const float4* ks0 = (const float4*)kb;
        #pragma unroll
        for (int it = 0; it < 8; it++) {
            R[2 * it]     = ks0[(it * 256 + t) * 2];
            R[2 * it + 1] = ks0[(it * 256 + t) * 2 + 1];
        }
    }
    // a_i = q_i . u + c (warp 0)
    if (t < 32) {
        const float cc = g_c;
        for (int i = 0; i < QL; i++) {
            float p = 0.f;
            #pragma unroll
            for (int m = 0; m < 8; m++) {
                int dd = t + 32 * m;
                p += __ldg(&qb[i * 256 + dd]) * g_u[dd];
            }
            #pragma unroll
            for (int o = 16; o > 0; o >>= 1) p += __shfl_xor_sync(0xffffffffu, p, o);
            if (t == 0) a_s[i] = p + cc;
        }
    }
    // STS stage 0
    #pragma unroll
    for (int it = 0; it < 8; it++) {
        int cidx = it * 256 + t;
        int row = cidx >> 5, c = cidx & 31;
        uint4 val = make_uint4(f2bf(R[2*it].x, R[2*it].y),   f2bf(R[2*it].z, R[2*it].w),
                               f2bf(R[2*it+1].x, R[2*it+1].y), f2bf(R[2*it+1].z, R[2*it+1].w));
        *(uint4*)(kb0 + row * 512 + ((c ^ (row & 7)) << 4)) = val;
    }
    __syncthreads();

    const float a_e  = a_s[2 * lq];
    const float a_o  = a_s[2 * lq + 1];
    const float a_e8 = a_s[2 * lq + 8];
    const float a_o8 = a_s[2 * lq + 9];
    float* cr = cred + (mt * 32 + lane) * 13;

    #pragma unroll
    for (int s = 0; s < 4; s++) {
        // issue loads for next stage (latency hidden under compute)
        if (s < 3) {
            const float4* ksn = (const float4*)(kb + (size_t)(64 * (s + 1)) * 256);
            #pragma unroll
            for (int it = 0; it < 8; it++) {
                R[2 * it]     = ksn[(it * 256 + t) * 2];
                R[2 * it + 1] = ksn[(it * 256 + t) * 2 + 1];
            }
        }
        // compute partial scores on buf[s&1]: warp = (mt, kh)
        const uint32_t kbase = smem_to_u32(kb0 + (s & 1) * 32768);
        float c0[4], c1[4], cw[4];
        #pragma unroll
        for (int i = 0; i < 4; i++) { c0[i] = 0.f; c1[i] = 0.f; cw[i] = 0.f; }
        const int krow = mt * 16 + (lane & 15);
        #pragma unroll
        for (int ki = 0; ki < 8; ki++) {
            const int ksx = kh * 8 + ki;
            unsigned a[4];
            int c = ksx * 2 + (lane >> 4);
            ldsm4(a, kbase + krow * 512 + ((c ^ (krow & 7)) << 4));
            int w0 = lr * 132 + ksx * 8 + lq;
            unsigned b00 = Qtw[w0],             b01 = Qtw[w0 + 4];
            unsigned b10 = Qtw[w0 + 8 * 132],   b11 = Qtw[w0 + 8 * 132 + 4];
            unsigned b20 = Qtw[w0 + 16 * 132],  b21 = Qtw[w0 + 16 * 132 + 4];
            mma16816(c0, a, b00, b01);
            mma16816(c1, a, b10, b11);
            mma16816(cw, a, b20, b21);
        }
        // cross-warp (ks-half) reduction
        if (kh == 1) {
            #pragma unroll
            for (int j = 0; j < 4; j++) { cr[j] = c0[j]; cr[4 + j] = c1[j]; cr[8 + j] = cw[j]; }
        }
        __syncthreads();
        if (kh == 0) {
            #pragma unroll
            for (int j = 0; j < 4; j++) { c0[j] += cr[j]; c1[j] += cr[4 + j]; cw[j] += cr[8 + j]; }
            float mr  = fmaxf(fmaxf(c0[0] + a_e, c0[1] + a_o), fmaxf(c1[0] + a_e8, c1[1] + a_o8));
            float mr8 = fmaxf(fmaxf(c0[2] + a_e, c0[3] + a_o), fmaxf(c1[2] + a_e8, c1[3] + a_o8));
            mr  = fmaxf(mr,  __shfl_xor_sync(0xffffffffu, mr, 1));
            mr  = fmaxf(mr,  __shfl_xor_sync(0xffffffffu, mr, 2));
            mr8 = fmaxf(mr8, __shfl_xor_sync(0xffffffffu, mr8, 1));
            mr8 = fmaxf(mr8, __shfl_xor_sync(0xffffffffu, mr8, 2));
            float wkr  = __shfl_sync(0xffffffffu, cw[0], lane & ~3);
            float wkr8 = __shfl_sync(0xffffffffu, cw[2], lane & ~3);
            if (lq == 0) {
                ta_s[s * 64 + mt * 16 + lr]     = wkr + mr;
                ta_s[s * 64 + mt * 16 + lr + 8] = wkr8 + mr8;
            }
        }
        // STS next stage into the other buffer
        if (s < 3) {
            unsigned char* nbuf = kb0 + ((s + 1) & 1) * 32768;
            #pragma unroll
            for (int it = 0; it < 8; it++) {
                int cidx = it * 256 + t;
                int row = cidx >> 5, c = cidx & 31;
                uint4 val = make_uint4(f2bf(R[2*it].x, R[2*it].y),   f2bf(R[2*it].z, R[2*it].w),
                                       f2bf(R[2*it+1].x, R[2*it+1].y), f2bf(R[2*it+1].z, R[2*it+1].w));
                *(uint4*)(nbuf + row * 512 + ((c ^ (row & 7)) << 4)) = val;
            }
        }
        __syncthreads();
    }

    // ---- normalize, mask, softmax (all 256); write attn + sA ----
    {
        float tv = ta_s[t];
        float ss = bsum(tv * tv, red_s, t);
        float inv = rsqrtf(ss);
        const int mm = g_mask_mode;
        bool masked;
        size_t mi = (size_t)pair * 256 + t;
        if (mm == 0)      masked = ((const unsigned char*)maskp)[mi] != 0;
        else if (mm == 1) masked = ((const int*)maskp)[mi] != 0;
        else              masked = ((const float*)maskp)[mi] != 0.f;
        float x = masked ? -10.f : tv * inv;
        float cnt = bsum(masked ? 0.f : 1.f, red_s, t);
        float mx = bmax(x, red_s, t);
        float ex = __expf(x - mx);
        float se = bsum(ex, red_s, t);
        float attn = (cnt == 0.f) ? 0.f : ex / se;
        g_attn[(size_t)pair * 256 + t] = attn;
        if (t == 0) g_sA[pair] = (cnt > 0.f) ? 1.f : 0.f;
    }
}

// ---------------- av_kernel: tvec partials, pure v stream ----------------
__global__ void __launch_bounds__(256)
av_kernel(const float* __restrict__ v)
{
    __shared__ float at[128];
    const int t = threadIdx.x;
    const int pair = blockIdx.x >> 1;
    const int half = blockIdx.x & 1;
    if (t < 128) at[t] = g_attn[(size_t)pair * 256 + half * 128 + t];
    __syncthreads();
    const float* vb = v + ((size_t)pair * 256 + half * 128) * 256;
    float acc = 0.f;
    #pragma unroll 16
    for (int r = 0; r < 128; r++)
        acc += at[r] * vb[r * 256 + t];
    g_tvh[(size_t)half * PAIRS * 256 + (size_t)pair * 256 + t] = acc;
}

// ---------------- out stage 1: partials over 64-j chunks ----------------
__global__ void __launch_bounds__(256)
out_part_kernel()
{
    __shared__ float tv[64 * 17];
    const int t = threadIdx.x;
    const int kc = blockIdx.x & 3;
    const int cg = (blockIdx.x >> 2) & 3;
    const int pg = blockIdx.x >> 4;
    const int p0 = pg * 16;
    const int c0 = cg * 64;
    const int j0 = kc * 64;
    const int c  = c0 + (t & 63);
    const int rg = t >> 6;

    #pragma unroll
    for (int it = 0; it < 4; it++) {
        int idx = it * 256 + t;
        int r = idx >> 6, j = idx & 63;
        size_t e = (size_t)(p0 + r) * 256 + j0 + j;
        tv[j * 17 + r] = g_tvh[e] + g_tvh[(size_t)PAIRS * 256 + e];
    }
    __syncthreads();
    float acc0 = 0.f, acc1 = 0.f, acc2 = 0.f, acc3 = 0.f;
    const float* Wcol = g_WvT + (size_t)j0 * 256 + c;
    #pragma unroll 8
    for (int j = 0; j < 64; j++) {
        float wv = __ldg(&Wcol[j * 256]);
        const float* T = &tv[j * 17];
        acc0 += T[rg]      * wv;
        acc1 += T[rg + 4]  * wv;
        acc2 += T[rg + 8]  * wv;
        acc3 += T[rg + 12] * wv;
    }
    float* op = g_opart + (size_t)kc * PAIRS * 256;
    op[(size_t)(p0 + rg)      * 256 + c] = acc0;
    op[(size_t)(p0 + rg + 4)  * 256 + c] = acc1;
    op[(size_t)(p0 + rg + 8)  * 256 + c] = acc2;
    op[(size_t)(p0 + rg + 12) * 256 + c] = acc3;
}

// ---------------- out stage 2: sum partials + bias ----------------
__global__ void __launch_bounds__(256)
out_sum_kernel(const float* __restrict__ vw_b, float* __restrict__ out)
{
    const int t = threadIdx.x;
    const int o0 = blockIdx.x * 1024 + t;
    #pragma unroll
    for (int it = 0; it < 4; it++) {
        int o = o0 + it * 256;
        int row = o >> 8, c = o & 255;
        float s = g_opart[o] + g_opart[o + PAIRS * 256]
                + g_opart[o + 2 * PAIRS * 256] + g_opart[o + 3 * PAIRS * 256];
        out[o] = s + g_sA[row] * __ldg(&vw_b[c]);
    }
}

extern "C" void kernel_launch(void* const* d_in, const int* in_sizes, int n_in,
                              void* d_out, int out_size)
{
    const float* q    = (const float*)d_in[0];
    const float* k    = (const float*)d_in[1];
    const float* v    = (const float*)d_in[2];
    const void*  m    = d_in[3];
    const float* qw_w = (const float*)d_in[4];
    const float* qw_b = (const float*)d_in[5];
    const float* kw_w = (const float*)d_in[6];
    const float* kw_b = (const float*)d_in[7];
    const float* vw_w = (const float*)d_in[8];
    const float* vw_b = (const float*)d_in[9];
    float* out = (float*)d_out;
    (void)in_sizes; (void)n_in; (void)out_size;

    cudaFuncSetAttribute(qt_gemm, cudaFuncAttributeMaxDynamicSharedMemorySize, QG_TOT);
    cudaFuncSetAttribute(fused_kernel, cudaFuncAttributeMaxDynamicSharedMemorySize, SM_TOT);

    setup_kernel<<<195, 256>>>(qw_w, qw_b, kw_w, kw_b, vw_w, m);
    qt_gemm<<<512, 256, QG_TOT>>>(q);
    fused_kernel<<<PAIRS, 256, SM_TOT>>>(q, k, m);
    av_kernel<<<2048, 256>>>(v);
    out_part_kernel<<<1024, 256>>>();
    out_sum_kernel<<<256, 256>>>(vw_b, out);
}